// round 1
// baseline (speedup 1.0000x reference)
#include <cuda_runtime.h>
#include <math.h>

#define En     200000
#define Pn     50000
#define Dn     128
#define NNZn   2000000
#define Cn     32
#define NSEEDn 320
#define G3     384   // 3*D

// ---------------- scratch (device globals; no allocation allowed) ----------------
__device__ float d_pmsg[(size_t)Pn * Dn];
__device__ float d_emsg[(size_t)En * Dn];
__device__ float d_gx[(size_t)En * G3];
__device__ float d_gh[(size_t)En * G3];
__device__ int   d_cntP[Pn];
__device__ int   d_offP[Pn + 1];
__device__ int   d_curP[Pn];
__device__ int   d_cntE[En];
__device__ int   d_offE[En + 1];
__device__ int   d_curE[En];
__device__ int   d_srcP[NNZn];
__device__ float d_valP[NNZn];
__device__ int   d_srcE[NNZn];
__device__ float d_valE[NNZn];
__device__ float d_smean[Dn];
__device__ int   d_partP[64];
__device__ int   d_partE[256];

// ---------------- CSR build ----------------
__global__ void k_zero_counts() {
    int i = blockIdx.x * blockDim.x + threadIdx.x;
    if (i < En) d_cntE[i] = 0;
    if (i < Pn) d_cntP[i] = 0;
}

__global__ void k_count(const int* __restrict__ rows, const int* __restrict__ cols) {
    int i = blockIdx.x * blockDim.x + threadIdx.x;
    if (i < NNZn) {
        atomicAdd(&d_cntE[rows[i]], 1);
        atomicAdd(&d_cntP[cols[i]], 1);
    }
}

__global__ void k_scan1(const int* __restrict__ cnt, int* __restrict__ off,
                        int* __restrict__ part, int n) {
    __shared__ int s[1024];
    int g = blockIdx.x * 1024 + threadIdx.x;
    s[threadIdx.x] = (g < n) ? cnt[g] : 0;
    __syncthreads();
    for (int o = 1; o < 1024; o <<= 1) {
        int t = (threadIdx.x >= o) ? s[threadIdx.x - o] : 0;
        __syncthreads();
        s[threadIdx.x] += t;
        __syncthreads();
    }
    if (g < n) off[g + 1] = s[threadIdx.x];
    if (threadIdx.x == 1023) part[blockIdx.x] = s[1023];
    if (g == 0) off[0] = 0;
}

__global__ void k_scan2(int* part, int n) {
    __shared__ int s[1024];
    s[threadIdx.x] = (threadIdx.x < n) ? part[threadIdx.x] : 0;
    __syncthreads();
    for (int o = 1; o < 1024; o <<= 1) {
        int t = (threadIdx.x >= o) ? s[threadIdx.x - o] : 0;
        __syncthreads();
        s[threadIdx.x] += t;
        __syncthreads();
    }
    if (threadIdx.x < n)
        part[threadIdx.x] = (threadIdx.x == 0) ? 0 : s[threadIdx.x - 1];
}

__global__ void k_scan3(int* off, const int* part, int n) {
    int g = blockIdx.x * 1024 + threadIdx.x;
    if (g < n) off[g + 1] += part[blockIdx.x];
}

__global__ void k_cursor_init() {
    int i = blockIdx.x * blockDim.x + threadIdx.x;
    if (i < En) d_curE[i] = d_offE[i];
    if (i < Pn) d_curP[i] = d_offP[i];
}

__global__ void k_fill(const int* __restrict__ rows, const int* __restrict__ cols,
                       const float* __restrict__ vals) {
    int i = blockIdx.x * blockDim.x + threadIdx.x;
    if (i < NNZn) {
        int r = rows[i], c = cols[i];
        float v = vals[i];
        int pp = atomicAdd(&d_curP[c], 1);
        d_srcP[pp] = r; d_valP[pp] = v;
        int pe = atomicAdd(&d_curE[r], 1);
        d_srcE[pe] = c; d_valE[pe] = v;
    }
}

// ---------------- seed mean ----------------
__global__ void k_seed_mean(const float* __restrict__ es, const int* __restrict__ sidx) {
    __shared__ float red[8][128];
    int d = threadIdx.x, ty = threadIdx.y;
    float s = 0.f;
    for (int i = ty; i < NSEEDn; i += 8)
        s += es[(size_t)sidx[i] * Dn + d];
    red[ty][d] = s;
    __syncthreads();
    if (ty == 0) {
        float tot = 0.f;
        #pragma unroll
        for (int j = 0; j < 8; j++) tot += red[j][d];
        d_smean[d] = tot * (1.f / NSEEDn);
    }
}

// ---------------- SpMM: one warp per segment, float4 lanes over D ----------------
__global__ void k_spmm(const float4* __restrict__ src, float4* __restrict__ dst,
                       const int* __restrict__ off, const int* __restrict__ sidx,
                       const float* __restrict__ sval, int nseg, int add_smean) {
    int seg = blockIdx.x * 4 + threadIdx.y;
    if (seg >= nseg) return;
    int lane = threadIdx.x;
    float4 acc;
    if (add_smean) acc = ((const float4*)d_smean)[lane];
    else           acc = make_float4(0.f, 0.f, 0.f, 0.f);
    int b = off[seg], e = off[seg + 1];
    for (int t = b; t < e; t++) {
        int r = sidx[t];
        float v = sval[t];
        float4 x = src[(size_t)r * 32 + lane];
        acc.x += x.x * v; acc.y += x.y * v; acc.z += x.z * v; acc.w += x.w * v;
    }
    dst[(size_t)seg * 32 + lane] = acc;
}

// ---------------- SGEMM: C[m][n] = sum_k A[m][k] * W[n][k]; K=128, N tile via blockIdx.y ----------------
__global__ void __launch_bounds__(256)
k_sgemm(const float* __restrict__ A, const float* __restrict__ W,
        float* __restrict__ Cmat, int M) {
    __shared__ float As[16][132];
    __shared__ float Bs[16][132];
    int m0 = blockIdx.x * 128;
    int n0 = blockIdx.y * 128;
    int tid = threadIdx.x;
    int tx = tid & 15, ty = tid >> 4;
    float acc[8][8];
    #pragma unroll
    for (int i = 0; i < 8; i++)
        #pragma unroll
        for (int j = 0; j < 8; j++) acc[i][j] = 0.f;

    for (int kt = 0; kt < 8; kt++) {
        int k0 = kt * 16;
        #pragma unroll
        for (int i = 0; i < 2; i++) {
            int idx = tid + i * 256;
            int row = idx >> 2, k4 = idx & 3;
            int m = m0 + row;
            float4 av = make_float4(0.f, 0.f, 0.f, 0.f);
            if (m < M) av = *(const float4*)(A + (size_t)m * 128 + k0 + k4 * 4);
            As[k4 * 4 + 0][row] = av.x; As[k4 * 4 + 1][row] = av.y;
            As[k4 * 4 + 2][row] = av.z; As[k4 * 4 + 3][row] = av.w;
            float4 bv = *(const float4*)(W + (size_t)(n0 + row) * 128 + k0 + k4 * 4);
            Bs[k4 * 4 + 0][row] = bv.x; Bs[k4 * 4 + 1][row] = bv.y;
            Bs[k4 * 4 + 2][row] = bv.z; Bs[k4 * 4 + 3][row] = bv.w;
        }
        __syncthreads();
        #pragma unroll
        for (int k = 0; k < 16; k++) {
            float a[8], b[8];
            *(float4*)(a)     = *(const float4*)&As[k][ty * 4];
            *(float4*)(a + 4) = *(const float4*)&As[k][64 + ty * 4];
            *(float4*)(b)     = *(const float4*)&Bs[k][tx * 4];
            *(float4*)(b + 4) = *(const float4*)&Bs[k][64 + tx * 4];
            #pragma unroll
            for (int i = 0; i < 8; i++)
                #pragma unroll
                for (int j = 0; j < 8; j++)
                    acc[i][j] += a[i] * b[j];
        }
        __syncthreads();
    }
    #pragma unroll
    for (int i = 0; i < 8; i++) {
        int m = m0 + ((i < 4) ? (ty * 4 + i) : (64 + ty * 4 + i - 4));
        if (m >= M) continue;
        float4 v1 = make_float4(acc[i][0], acc[i][1], acc[i][2], acc[i][3]);
        float4 v2 = make_float4(acc[i][4], acc[i][5], acc[i][6], acc[i][7]);
        *(float4*)(Cmat + (size_t)m * G3 + n0 + tx * 4) = v1;
        *(float4*)(Cmat + (size_t)m * G3 + n0 + 64 + tx * 4) = v2;
    }
}

// ---------------- GRU gates ----------------
__device__ __forceinline__ float sigmf(float x) { return 1.f / (1.f + expf(-x)); }

__global__ void k_gate(float* __restrict__ h, const float* __restrict__ gx,
                       const float* __restrict__ gh, const float* __restrict__ bih,
                       const float* __restrict__ bhh, int M) {
    int i = blockIdx.x * blockDim.x + threadIdx.x;
    if (i >= M * 32) return;
    int m = i >> 5, q = i & 31;
    const float4* gx4 = (const float4*)(gx + (size_t)m * G3);
    const float4* gh4 = (const float4*)(gh + (size_t)m * G3);
    float4 xr = gx4[q], xz = gx4[32 + q], xn = gx4[64 + q];
    float4 hr = gh4[q], hz = gh4[32 + q], hn = gh4[64 + q];
    const float4* bi4 = (const float4*)bih;
    const float4* bh4 = (const float4*)bhh;
    float4 bir = bi4[q], biz = bi4[32 + q], bin_ = bi4[64 + q];
    float4 bhr = bh4[q], bhz = bh4[32 + q], bhn = bh4[64 + q];
    float4* hp = (float4*)(h + (size_t)m * Dn);
    float4 hv = hp[q];
    float r, z, n;
#define GATE(c) \
    r = sigmf(xr.c + bir.c + hr.c + bhr.c); \
    z = sigmf(xz.c + biz.c + hz.c + bhz.c); \
    n = tanhf(xn.c + bin_.c + r * (hn.c + bhn.c)); \
    hv.c = (1.f - z) * n + z * hv.c;
    GATE(x) GATE(y) GATE(z) GATE(w)
#undef GATE
    hp[q] = hv;
}

// ---------------- final FC: logits = es @ fc_w^T + fc_b ----------------
__global__ void k_fc(const float* __restrict__ es, const float* __restrict__ fcw,
                     const float* __restrict__ fcb, float* __restrict__ logits) {
    __shared__ float Wt[128][33];
    __shared__ float rowbuf[8][128];
    int tid = threadIdx.x;
    #pragma unroll
    for (int i = 0; i < 4; i++) {
        int idx = tid + i * 256;          // [32 j][32 k4]
        int j = idx >> 5, k4 = idx & 31;
        float4 w = ((const float4*)fcw)[j * 32 + k4];
        Wt[k4 * 4 + 0][j] = w.x; Wt[k4 * 4 + 1][j] = w.y;
        Wt[k4 * 4 + 2][j] = w.z; Wt[k4 * 4 + 3][j] = w.w;
    }
    __syncthreads();
    int w = tid >> 5, lane = tid & 31;
    int base = blockIdx.x * 32;
    for (int it = 0; it < 4; it++) {
        int m = base + w * 4 + it;
        if (m >= En) continue;
        float4 rv = ((const float4*)(es + (size_t)m * 128))[lane];
        ((float4*)rowbuf[w])[lane] = rv;
        __syncwarp();
        float acc = fcb[lane];
        #pragma unroll
        for (int k = 0; k < 128; k++)
            acc += rowbuf[w][k] * Wt[k][lane];
        logits[(size_t)m * Cn + lane] = acc;
        __syncwarp();
    }
}

// ---------------- host orchestration ----------------
extern "C" void kernel_launch(void* const* d_in, const int* in_sizes, int n_in,
                              void* d_out, int out_size) {
    (void)in_sizes; (void)n_in; (void)out_size;
    const int*   seed_index = (const int*)d_in[0];
    const float* es_in  = (const float*)d_in[1];
    const float* ps_in  = (const float*)d_in[2];
    const int*   rows   = (const int*)d_in[3];
    const int*   cols   = (const int*)d_in[4];
    const float* vals   = (const float*)d_in[5];
    const float* fcw    = (const float*)d_in[22];
    const float* fcb    = (const float*)d_in[23];

    float* out       = (float*)d_out;
    float* out_logit = out;
    float* out_es    = out + (size_t)En * Cn;
    float* out_ps    = out_es + (size_t)En * Dn;

    // symbol addresses (host-side only; free at replay time)
    void *pOffP, *pOffE, *pSrcP, *pSrcE, *pValP, *pValE;
    void *pPartP, *pPartE, *pCntP, *pCntE, *pPmsg, *pEmsg, *pGx, *pGh;
    cudaGetSymbolAddress(&pOffP, d_offP);
    cudaGetSymbolAddress(&pOffE, d_offE);
    cudaGetSymbolAddress(&pSrcP, d_srcP);
    cudaGetSymbolAddress(&pSrcE, d_srcE);
    cudaGetSymbolAddress(&pValP, d_valP);
    cudaGetSymbolAddress(&pValE, d_valE);
    cudaGetSymbolAddress(&pPartP, d_partP);
    cudaGetSymbolAddress(&pPartE, d_partE);
    cudaGetSymbolAddress(&pCntP, d_cntP);
    cudaGetSymbolAddress(&pCntE, d_cntE);
    cudaGetSymbolAddress(&pPmsg, d_pmsg);
    cudaGetSymbolAddress(&pEmsg, d_emsg);
    cudaGetSymbolAddress(&pGx, d_gx);
    cudaGetSymbolAddress(&pGh, d_gh);

    cudaMemcpyAsync(out_es, es_in, (size_t)En * Dn * sizeof(float), cudaMemcpyDeviceToDevice);
    cudaMemcpyAsync(out_ps, ps_in, (size_t)Pn * Dn * sizeof(float), cudaMemcpyDeviceToDevice);

    // CSR build (both directions)
    k_zero_counts<<<(En + 255) / 256, 256>>>();
    k_count<<<(NNZn + 255) / 256, 256>>>(rows, cols);
    int nbP = (Pn + 1023) / 1024;   // 49
    int nbE = (En + 1023) / 1024;   // 196
    k_scan1<<<nbP, 1024>>>((const int*)pCntP, (int*)pOffP, (int*)pPartP, Pn);
    k_scan2<<<1, 1024>>>((int*)pPartP, nbP);
    k_scan3<<<nbP, 1024>>>((int*)pOffP, (const int*)pPartP, Pn);
    k_scan1<<<nbE, 1024>>>((const int*)pCntE, (int*)pOffE, (int*)pPartE, En);
    k_scan2<<<1, 1024>>>((int*)pPartE, nbE);
    k_scan3<<<nbE, 1024>>>((int*)pOffE, (const int*)pPartE, En);
    k_cursor_init<<<(En + 255) / 256, 256>>>();
    k_fill<<<(NNZn + 255) / 256, 256>>>(rows, cols, vals);

    dim3 spmmB(32, 4);
    dim3 gP((Pn + 127) / 128, 3);
    dim3 gE((En + 127) / 128, 3);

    for (int l = 0; l < 2; l++) {
        const float* eWih = (const float*)d_in[6 + l * 8 + 0];
        const float* eWhh = (const float*)d_in[6 + l * 8 + 1];
        const float* ebih = (const float*)d_in[6 + l * 8 + 2];
        const float* ebhh = (const float*)d_in[6 + l * 8 + 3];
        const float* pWih = (const float*)d_in[6 + l * 8 + 4];
        const float* pWhh = (const float*)d_in[6 + l * 8 + 5];
        const float* pbih = (const float*)d_in[6 + l * 8 + 6];
        const float* pbhh = (const float*)d_in[6 + l * 8 + 7];

        k_seed_mean<<<1, dim3(128, 8)>>>(out_es, seed_index);

        // p_msg = segment_sum(es[row]*w, col); ps = GRU(p_msg, ps)
        k_spmm<<<(Pn + 3) / 4, spmmB>>>((const float4*)out_es, (float4*)pPmsg,
                                        (const int*)pOffP, (const int*)pSrcP,
                                        (const float*)pValP, Pn, 0);
        k_sgemm<<<gP, 256>>>((const float*)pPmsg, pWih, (float*)pGx, Pn);
        k_sgemm<<<gP, 256>>>(out_ps, pWhh, (float*)pGh, Pn);
        k_gate<<<(Pn * 32 + 255) / 256, 256>>>(out_ps, (const float*)pGx,
                                               (const float*)pGh, pbih, pbhh, Pn);

        // e_msg = segment_sum(ps[col]*w, row) + seed_mean; es = GRU(e_msg, es)
        k_spmm<<<(En + 3) / 4, spmmB>>>((const float4*)out_ps, (float4*)pEmsg,
                                        (const int*)pOffE, (const int*)pSrcE,
                                        (const float*)pValE, En, 1);
        k_sgemm<<<gE, 256>>>((const float*)pEmsg, eWih, (float*)pGx, En);
        k_sgemm<<<gE, 256>>>(out_es, eWhh, (float*)pGh, En);
        k_gate<<<(En * 32 + 255) / 256, 256>>>(out_es, (const float*)pGx,
                                               (const float*)pGh, ebih, ebhh, En);
    }

    k_fc<<<En / 32, 256>>>(out_es, fcw, fcb, out_logit);
}

// round 3
// speedup vs baseline: 1.2747x; 1.2747x over previous
#include <cuda_runtime.h>
#include <math.h>
#include <stdint.h>

#define En     200000
#define Pn     50000
#define Dn     128
#define NNZn   2000000
#define Cn     32
#define NSEEDn 320
#define G3     384   // 3*D

// ---------------- scratch (device globals; no allocation allowed) ----------------
__device__ float d_pmsg[(size_t)Pn * Dn];
__device__ float d_emsg[(size_t)En * Dn];
__device__ int   d_cntP[Pn];
__device__ int   d_offP[Pn + 1];
__device__ int   d_curP[Pn];
__device__ int   d_cntE[En];
__device__ int   d_offE[En + 1];
__device__ int   d_curE[En];
__device__ int   d_srcP[NNZn];
__device__ float d_valP[NNZn];
__device__ int   d_srcE[NNZn];
__device__ float d_valE[NNZn];
__device__ float d_smean[Dn];
__device__ int   d_partP[64];
__device__ int   d_partE[256];
__device__ uint32_t d_wtih[G3 * Dn];   // tf32, permuted
__device__ uint32_t d_wthh[G3 * Dn];   // tf32, permuted

// ---------------- CSR build ----------------
__global__ void k_zero_counts() {
    int i = blockIdx.x * blockDim.x + threadIdx.x;
    if (i < En) d_cntE[i] = 0;
    if (i < Pn) d_cntP[i] = 0;
}

__global__ void k_count(const int* __restrict__ rows, const int* __restrict__ cols) {
    int i = blockIdx.x * blockDim.x + threadIdx.x;
    if (i < NNZn) {
        atomicAdd(&d_cntE[rows[i]], 1);
        atomicAdd(&d_cntP[cols[i]], 1);
    }
}

__global__ void k_scan1(const int* __restrict__ cnt, int* __restrict__ off,
                        int* __restrict__ part, int n) {
    __shared__ int s[1024];
    int g = blockIdx.x * 1024 + threadIdx.x;
    s[threadIdx.x] = (g < n) ? cnt[g] : 0;
    __syncthreads();
    for (int o = 1; o < 1024; o <<= 1) {
        int t = (threadIdx.x >= o) ? s[threadIdx.x - o] : 0;
        __syncthreads();
        s[threadIdx.x] += t;
        __syncthreads();
    }
    if (g < n) off[g + 1] = s[threadIdx.x];
    if (threadIdx.x == 1023) part[blockIdx.x] = s[1023];
    if (g == 0) off[0] = 0;
}

__global__ void k_scan2(int* part, int n) {
    __shared__ int s[1024];
    s[threadIdx.x] = (threadIdx.x < n) ? part[threadIdx.x] : 0;
    __syncthreads();
    for (int o = 1; o < 1024; o <<= 1) {
        int t = (threadIdx.x >= o) ? s[threadIdx.x - o] : 0;
        __syncthreads();
        s[threadIdx.x] += t;
        __syncthreads();
    }
    if (threadIdx.x < n)
        part[threadIdx.x] = (threadIdx.x == 0) ? 0 : s[threadIdx.x - 1];
}

__global__ void k_scan3(int* off, const int* part, int n) {
    int g = blockIdx.x * 1024 + threadIdx.x;
    if (g < n) off[g + 1] += part[blockIdx.x];
}

__global__ void k_cursor_init() {
    int i = blockIdx.x * blockDim.x + threadIdx.x;
    if (i < En) d_curE[i] = d_offE[i];
    if (i < Pn) d_curP[i] = d_offP[i];
}

__global__ void k_fill(const int* __restrict__ rows, const int* __restrict__ cols,
                       const float* __restrict__ vals) {
    int i = blockIdx.x * blockDim.x + threadIdx.x;
    if (i < NNZn) {
        int r = rows[i], c = cols[i];
        float v = vals[i];
        int pp = atomicAdd(&d_curP[c], 1);
        d_srcP[pp] = r; d_valP[pp] = v;
        int pe = atomicAdd(&d_curE[r], 1);
        d_srcE[pe] = c; d_valE[pe] = v;
    }
}

// ---------------- seed mean ----------------
__global__ void k_seed_mean(const float* __restrict__ es, const int* __restrict__ sidx) {
    __shared__ float red[8][128];
    int d = threadIdx.x, ty = threadIdx.y;
    float s = 0.f;
    for (int i = ty; i < NSEEDn; i += 8)
        s += es[(size_t)sidx[i] * Dn + d];
    red[ty][d] = s;
    __syncthreads();
    if (ty == 0) {
        float tot = 0.f;
        #pragma unroll
        for (int j = 0; j < 8; j++) tot += red[j][d];
        d_smean[d] = tot * (1.f / NSEEDn);
    }
}

// ---------------- SpMM: one warp per segment, float4 lanes over D ----------------
__global__ void k_spmm(const float4* __restrict__ src, float4* __restrict__ dst,
                       const int* __restrict__ off, const int* __restrict__ sidx,
                       const float* __restrict__ sval, int nseg, int add_smean) {
    int seg = blockIdx.x * 4 + threadIdx.y;
    if (seg >= nseg) return;
    int lane = threadIdx.x;
    float4 acc;
    if (add_smean) acc = ((const float4*)d_smean)[lane];
    else           acc = make_float4(0.f, 0.f, 0.f, 0.f);
    int b = off[seg], e = off[seg + 1];
    int t = b;
    for (; t + 2 <= e; t += 2) {
        int r0 = sidx[t], r1 = sidx[t + 1];
        float v0 = sval[t], v1 = sval[t + 1];
        float4 x0 = src[(size_t)r0 * 32 + lane];
        float4 x1 = src[(size_t)r1 * 32 + lane];
        acc.x += x0.x * v0 + x1.x * v1;
        acc.y += x0.y * v0 + x1.y * v1;
        acc.z += x0.z * v0 + x1.z * v1;
        acc.w += x0.w * v0 + x1.w * v1;
    }
    if (t < e) {
        int r0 = sidx[t]; float v0 = sval[t];
        float4 x0 = src[(size_t)r0 * 32 + lane];
        acc.x += x0.x * v0; acc.y += x0.y * v0;
        acc.z += x0.z * v0; acc.w += x0.w * v0;
    }
    dst[(size_t)seg * 32 + lane] = acc;
}

// ---------------- weight prep: fp32 -> tf32, permuted rows ----------------
// permuted row j -> source row part*128 + w*32 + idx, w=j/96, part=(j%96)/32, idx=j%32
__device__ __forceinline__ uint32_t f2tf32(float f) {
    uint32_t u;
    asm("cvt.rna.tf32.f32 %0, %1;" : "=r"(u) : "f"(f));
    return u;
}

__global__ void k_wprep(const float* __restrict__ Wih, const float* __restrict__ Whh) {
    int j = blockIdx.x;
    int k = threadIdx.x;
    int w = j / 96, rem = j % 96;
    int part = rem / 32, idx = rem % 32;
    int srow = part * 128 + w * 32 + idx;
    d_wtih[j * 128 + k] = f2tf32(Wih[srow * 128 + k]);
    d_wthh[j * 128 + k] = f2tf32(Whh[srow * 128 + k]);
}

// ---------------- fused GRU: gx=msg@Wih^T, gh=h@Whh^T, gate, h update ----------------
__device__ __forceinline__ float sigmf(float x) { return 1.f / (1.f + expf(-x)); }

#define MMA_TF32(acc, a0, a1, a2, a3, b0, b1)                               \
    asm volatile("mma.sync.aligned.m16n8k8.row.col.f32.tf32.tf32.f32 "      \
                 "{%0,%1,%2,%3}, {%4,%5,%6,%7}, {%8,%9}, {%0,%1,%2,%3};"    \
                 : "+f"(acc[0]), "+f"(acc[1]), "+f"(acc[2]), "+f"(acc[3])   \
                 : "r"(a0), "r"(a1), "r"(a2), "r"(a3), "r"(b0), "r"(b1));

// smem layout (u32 units, row stride 36):
//   sAx @ 0      (32*36)   msg tile (tf32)
//   sAh @ 1152   (32*36)   h tile (tf32)
//   sBi @ 2304   (384*36)  Wih tile (tf32, permuted)
//   sBh @ 16128  (384*36)  Whh tile
#define SMEM_U32 29952

__global__ void __launch_bounds__(256, 1)
k_gru_fused(const float* __restrict__ msg, float* __restrict__ h,
            const float* __restrict__ bih, const float* __restrict__ bhh, int M) {
    extern __shared__ uint32_t su[];
    uint32_t* sAx = su;
    uint32_t* sAh = su + 1152;
    uint32_t* sBi = su + 2304;
    uint32_t* sBh = su + 16128;

    int tid = threadIdx.x;
    int lane = tid & 31;
    int wid = tid >> 5;
    int rowHalf = wid >> 2;       // 0/1
    int cg = wid & 3;             // col group: 32 gate-cols
    int mr = rowHalf * 16;        // warp row base in tile
    int nb = cg * 96;             // warp permuted-col base
    int m0 = blockIdx.x * 32;

    float accX[12][4], accH[12][4];
    #pragma unroll
    for (int t = 0; t < 12; t++)
        #pragma unroll
        for (int i = 0; i < 4; i++) { accX[t][i] = 0.f; accH[t][i] = 0.f; }

    const float4* msg4 = (const float4*)msg;
    const float4* h4   = (const float4*)h;
    const uint4*  wi4  = (const uint4*)d_wtih;
    const uint4*  wh4  = (const uint4*)d_wthh;

    for (int kc = 0; kc < 4; kc++) {
        // ---- load A tiles (msg, h): 512 float4, 2 per thread ----
        #pragma unroll
        for (int i = 0; i < 2; i++) {
            int id = tid + i * 256;           // [0,512)
            int mtx = id >> 8;                // 0: msg, 1: h
            int r = (id >> 3) & 31;
            int f4 = id & 7;
            float4 v = make_float4(0.f, 0.f, 0.f, 0.f);
            int grow = m0 + r;
            if (grow < M)
                v = (mtx ? h4 : msg4)[(size_t)grow * 32 + kc * 8 + f4];
            uint4 o;
            o.x = f2tf32(v.x); o.y = f2tf32(v.y);
            o.z = f2tf32(v.z); o.w = f2tf32(v.w);
            uint32_t* dst = mtx ? sAh : sAx;
            *(uint4*)(dst + r * 36 + f4 * 4) = o;
        }
        // ---- load B tiles (Wih, Whh): 6144 uint4, 24 per thread ----
        #pragma unroll
        for (int i = 0; i < 24; i++) {
            int id = tid + i * 256;           // [0,6144)
            int q = id >> 3;                  // [0,768)
            int mtx = (q >= 384) ? 1 : 0;
            int r = q - mtx * 384;
            int f4 = id & 7;
            uint4 v = (mtx ? wh4 : wi4)[r * 32 + kc * 8 + f4];
            uint32_t* dst = mtx ? sBh : sBi;
            *(uint4*)(dst + r * 36 + f4 * 4) = v;
        }
        __syncthreads();

        // ---- compute ----
        #pragma unroll
        for (int kt = 0; kt < 4; kt++) {
            int k1 = kt * 8 + (lane & 3);
            int ar = (mr + (lane >> 2)) * 36 + k1;
            uint32_t ax0 = sAx[ar],       ax1 = sAx[ar + 8 * 36];
            uint32_t ax2 = sAx[ar + 4],   ax3 = sAx[ar + 8 * 36 + 4];
            uint32_t ah0 = sAh[ar],       ah1 = sAh[ar + 8 * 36];
            uint32_t ah2 = sAh[ar + 4],   ah3 = sAh[ar + 8 * 36 + 4];
            #pragma unroll
            for (int t = 0; t < 12; t++) {
                int br = (nb + t * 8 + (lane >> 2)) * 36 + k1;
                uint32_t bi0 = sBi[br], bi1 = sBi[br + 4];
                uint32_t bh0 = sBh[br], bh1 = sBh[br + 4];
                MMA_TF32(accX[t], ax0, ax1, ax2, ax3, bi0, bi1);
                MMA_TF32(accH[t], ah0, ah1, ah2, ah3, bh0, bh1);
            }
        }
        __syncthreads();
    }

    // ---- gate epilogue, in-register ----
    int c2 = (lane & 3) * 2;
    int r0 = m0 + mr + (lane >> 2);
    #pragma unroll
    for (int t2 = 0; t2 < 4; t2++) {
        #pragma unroll
        for (int half = 0; half < 2; half++) {
            int g = cg * 32 + t2 * 8 + c2 + half;
            float bir = bih[g] + bhh[g];
            float biz = bih[128 + g] + bhh[128 + g];
            float bin_ = bih[256 + g];
            float bhn = bhh[256 + g];
            #pragma unroll
            for (int rr = 0; rr < 2; rr++) {
                int row = r0 + rr * 8;
                if (row >= M) continue;
                int ci = rr * 2 + half;
                float r = sigmf(accX[t2][ci] + accH[t2][ci] + bir);
                float z = sigmf(accX[t2 + 4][ci] + accH[t2 + 4][ci] + biz);
                float nn = tanhf(accX[t2 + 8][ci] + bin_ + r * (accH[t2 + 8][ci] + bhn));
                float ho = h[(size_t)row * 128 + g];
                h[(size_t)row * 128 + g] = (1.f - z) * nn + z * ho;
            }
        }
    }
}

// ---------------- final FC: logits = es @ fc_w^T + fc_b ----------------
__global__ void k_fc(const float* __restrict__ es, const float* __restrict__ fcw,
                     const float* __restrict__ fcb, float* __restrict__ logits) {
    __shared__ float Wt[128][33];
    __shared__ float rowbuf[8][128];
    int tid = threadIdx.x;
    #pragma unroll
    for (int i = 0; i < 4; i++) {
        int idx = tid + i * 256;          // [32 j][32 k4]
        int j = idx >> 5, k4 = idx & 31;
        float4 w = ((const float4*)fcw)[j * 32 + k4];
        Wt[k4 * 4 + 0][j] = w.x; Wt[k4 * 4 + 1][j] = w.y;
        Wt[k4 * 4 + 2][j] = w.z; Wt[k4 * 4 + 3][j] = w.w;
    }
    __syncthreads();
    int w = tid >> 5, lane = tid & 31;
    int base = blockIdx.x * 32;
    for (int it = 0; it < 4; it++) {
        int m = base + w * 4 + it;
        if (m >= En) continue;
        float4 rv = ((const float4*)(es + (size_t)m * 128))[lane];
        ((float4*)rowbuf[w])[lane] = rv;
        __syncwarp();
        float acc = fcb[lane];
        #pragma unroll
        for (int k = 0; k < 128; k++)
            acc += rowbuf[w][k] * Wt[k][lane];
        logits[(size_t)m * Cn + lane] = acc;
        __syncwarp();
    }
}

// ---------------- host orchestration ----------------
extern "C" void kernel_launch(void* const* d_in, const int* in_sizes, int n_in,
                              void* d_out, int out_size) {
    (void)in_sizes; (void)n_in; (void)out_size;
    const int*   seed_index = (const int*)d_in[0];
    const float* es_in  = (const float*)d_in[1];
    const float* ps_in  = (const float*)d_in[2];
    const int*   rows   = (const int*)d_in[3];
    const int*   cols   = (const int*)d_in[4];
    const float* vals   = (const float*)d_in[5];
    const float* fcw    = (const float*)d_in[22];
    const float* fcb    = (const float*)d_in[23];

    float* out       = (float*)d_out;
    float* out_logit = out;
    float* out_es    = out + (size_t)En * Cn;
    float* out_ps    = out_es + (size_t)En * Dn;

    // idempotent; called every time (no static state allowed)
    cudaFuncSetAttribute(k_gru_fused, cudaFuncAttributeMaxDynamicSharedMemorySize,
                         SMEM_U32 * 4);

    void *pOffP, *pOffE, *pSrcP, *pSrcE, *pValP, *pValE;
    void *pPartP, *pPartE, *pCntP, *pCntE, *pPmsg, *pEmsg;
    cudaGetSymbolAddress(&pOffP, d_offP);
    cudaGetSymbolAddress(&pOffE, d_offE);
    cudaGetSymbolAddress(&pSrcP, d_srcP);
    cudaGetSymbolAddress(&pSrcE, d_srcE);
    cudaGetSymbolAddress(&pValP, d_valP);
    cudaGetSymbolAddress(&pValE, d_valE);
    cudaGetSymbolAddress(&pPartP, d_partP);
    cudaGetSymbolAddress(&pPartE, d_partE);
    cudaGetSymbolAddress(&pCntP, d_cntP);
    cudaGetSymbolAddress(&pCntE, d_cntE);
    cudaGetSymbolAddress(&pPmsg, d_pmsg);
    cudaGetSymbolAddress(&pEmsg, d_emsg);

    cudaMemcpyAsync(out_es, es_in, (size_t)En * Dn * sizeof(float), cudaMemcpyDeviceToDevice);
    cudaMemcpyAsync(out_ps, ps_in, (size_t)Pn * Dn * sizeof(float), cudaMemcpyDeviceToDevice);

    // CSR build (both directions)
    k_zero_counts<<<(En + 255) / 256, 256>>>();
    k_count<<<(NNZn + 255) / 256, 256>>>(rows, cols);
    int nbP = (Pn + 1023) / 1024;   // 49
    int nbE = (En + 1023) / 1024;   // 196
    k_scan1<<<nbP, 1024>>>((const int*)pCntP, (int*)pOffP, (int*)pPartP, Pn);
    k_scan2<<<1, 1024>>>((int*)pPartP, nbP);
    k_scan3<<<nbP, 1024>>>((int*)pOffP, (const int*)pPartP, Pn);
    k_scan1<<<nbE, 1024>>>((const int*)pCntE, (int*)pOffE, (int*)pPartE, En);
    k_scan2<<<1, 1024>>>((int*)pPartE, nbE);
    k_scan3<<<nbE, 1024>>>((int*)pOffE, (const int*)pPartE, En);
    k_cursor_init<<<(En + 255) / 256, 256>>>();
    k_fill<<<(NNZn + 255) / 256, 256>>>(rows, cols, vals);

    dim3 spmmB(32, 4);
    size_t smemB = SMEM_U32 * 4;

    for (int l = 0; l < 2; l++) {
        const float* eWih = (const float*)d_in[6 + l * 8 + 0];
        const float* eWhh = (const float*)d_in[6 + l * 8 + 1];
        const float* ebih = (const float*)d_in[6 + l * 8 + 2];
        const float* ebhh = (const float*)d_in[6 + l * 8 + 3];
        const float* pWih = (const float*)d_in[6 + l * 8 + 4];
        const float* pWhh = (const float*)d_in[6 + l * 8 + 5];
        const float* pbih = (const float*)d_in[6 + l * 8 + 6];
        const float* pbhh = (const float*)d_in[6 + l * 8 + 7];

        k_seed_mean<<<1, dim3(128, 8)>>>(out_es, seed_index);

        // p_msg = segment_sum(es[row]*w, col); ps = GRU(p_msg, ps)
        k_spmm<<<(Pn + 3) / 4, spmmB>>>((const float4*)out_es, (float4*)pPmsg,
                                        (const int*)pOffP, (const int*)pSrcP,
                                        (const float*)pValP, Pn, 0);
        k_wprep<<<G3, 128>>>(pWih, pWhh);
        k_gru_fused<<<(Pn + 31) / 32, 256, smemB>>>((const float*)pPmsg, out_ps,
                                                    pbih, pbhh, Pn);

        // e_msg = segment_sum(ps[col]*w, row) + seed_mean; es = GRU(e_msg, es)
        k_spmm<<<(En + 3) / 4, spmmB>>>((const float4*)out_ps, (float4*)pEmsg,
                                        (const int*)pOffE, (const int*)pSrcE,
                                        (const float*)pValE, En, 1);
        k_wprep<<<G3, 128>>>(eWih, eWhh);
        k_gru_fused<<<(En + 31) / 32, 256, smemB>>>((const float*)pEmsg, out_es,
                                                    ebih, ebhh, En);
    }

    k_fc<<<En / 32, 256>>>(out_es, fcw, fcb, out_logit);
}

// round 5
// speedup vs baseline: 1.3274x; 1.0413x over previous
#include <cuda_runtime.h>
#include <math.h>
#include <stdint.h>

#define En     200000
#define Pn     50000
#define Dn     128
#define NNZn   2000000
#define Cn     32
#define NSEEDn 320
#define G3     384   // 3*D

// ---------------- scratch (device globals; no allocation allowed) ----------------
__device__ float d_pmsg[(size_t)Pn * Dn];
__device__ float d_emsg[(size_t)En * Dn];
__device__ int   d_cntP[Pn];
__device__ int   d_offP[Pn + 1];
__device__ int   d_curP[Pn];
__device__ int   d_cntE[En];
__device__ int   d_offE[En + 1];
__device__ int   d_curE[En];
__device__ int2  d_eiP[NNZn];          // (src_row, val_bits)
__device__ int2  d_eiE[NNZn];          // (src_col, val_bits)
__device__ float d_smean[Dn];
__device__ int   d_partP[64];
__device__ int   d_partE[256];
__device__ uint32_t d_wtih[G3 * Dn];   // tf32, permuted
__device__ uint32_t d_wthh[G3 * Dn];   // tf32, permuted

#define NBP ((Pn + 1023) / 1024)   // 49
#define NBE ((En + 1023) / 1024)   // 196

// ---------------- CSR build ----------------
__global__ void k_zero_counts() {
    int i = blockIdx.x * blockDim.x + threadIdx.x;
    if (i < En) d_cntE[i] = 0;
    if (i < Pn) d_cntP[i] = 0;
}

__global__ void k_count(const int* __restrict__ rows, const int* __restrict__ cols) {
    int i = blockIdx.x * blockDim.x + threadIdx.x;
    if (i < NNZn) {
        atomicAdd(&d_cntE[rows[i]], 1);
        atomicAdd(&d_cntP[cols[i]], 1);
    }
}

// fused P+E block scans: blocks [0,NBP) -> P, [NBP,NBP+NBE) -> E
__global__ void k_scan1() {
    __shared__ int s[1024];
    int isE = (blockIdx.x >= NBP);
    int b = isE ? blockIdx.x - NBP : blockIdx.x;
    const int* cnt = isE ? d_cntE : d_cntP;
    int* off = isE ? d_offE : d_offP;
    int* part = isE ? d_partE : d_partP;
    int n = isE ? En : Pn;
    int g = b * 1024 + threadIdx.x;
    s[threadIdx.x] = (g < n) ? cnt[g] : 0;
    __syncthreads();
    for (int o = 1; o < 1024; o <<= 1) {
        int t = (threadIdx.x >= o) ? s[threadIdx.x - o] : 0;
        __syncthreads();
        s[threadIdx.x] += t;
        __syncthreads();
    }
    if (g < n) off[g + 1] = s[threadIdx.x];
    if (threadIdx.x == 1023) part[b] = s[1023];
    if (g == 0) off[0] = 0;
}

__global__ void k_scan2() {
    __shared__ int s[1024];
    int isE = (blockIdx.x == 1);
    int* part = isE ? d_partE : d_partP;
    int n = isE ? NBE : NBP;
    s[threadIdx.x] = (threadIdx.x < n) ? part[threadIdx.x] : 0;
    __syncthreads();
    for (int o = 1; o < 1024; o <<= 1) {
        int t = (threadIdx.x >= o) ? s[threadIdx.x - o] : 0;
        __syncthreads();
        s[threadIdx.x] += t;
        __syncthreads();
    }
    if (threadIdx.x < n)
        part[threadIdx.x] = (threadIdx.x == 0) ? 0 : s[threadIdx.x - 1];
}

// fused: add block prefix + cursor init
__global__ void k_scan3() {
    int isE = (blockIdx.x >= NBP);
    int b = isE ? blockIdx.x - NBP : blockIdx.x;
    int* off = isE ? d_offE : d_offP;
    int* cur = isE ? d_curE : d_curP;
    const int* part = isE ? d_partE : d_partP;
    int n = isE ? En : Pn;
    int g = b * 1024 + threadIdx.x;
    if (g < n) {
        int v = off[g + 1] + part[b];
        off[g + 1] = v;
        if (g + 1 < n) cur[g + 1] = v;
    }
    if (g == 0) cur[0] = 0;
}

__global__ void k_fill(const int* __restrict__ rows, const int* __restrict__ cols,
                       const float* __restrict__ vals) {
    int i = blockIdx.x * blockDim.x + threadIdx.x;
    if (i < NNZn) {
        int r = rows[i], c = cols[i];
        int vb = __float_as_int(vals[i]);
        int pp = atomicAdd(&d_curP[c], 1);
        d_eiP[pp] = make_int2(r, vb);
        int pe = atomicAdd(&d_curE[r], 1);
        d_eiE[pe] = make_int2(c, vb);
    }
}

// ---------------- seed mean ----------------
__global__ void k_seed_mean(const float* __restrict__ es, const int* __restrict__ sidx) {
    __shared__ float red[8][128];
    int d = threadIdx.x, ty = threadIdx.y;
    float s = 0.f;
    for (int i = ty; i < NSEEDn; i += 8)
        s += es[(size_t)sidx[i] * Dn + d];
    red[ty][d] = s;
    __syncthreads();
    if (ty == 0) {
        float tot = 0.f;
        #pragma unroll
        for (int j = 0; j < 8; j++) tot += red[j][d];
        d_smean[d] = tot * (1.f / NSEEDn);
    }
}

// ---------------- SpMM: one warp per segment, 4-edge unroll for MLP ----------------
__global__ void k_spmm(const float4* __restrict__ src, float4* __restrict__ dst,
                       const int* __restrict__ off, const int2* __restrict__ ei,
                       int nseg, int add_smean) {
    int seg = blockIdx.x * 8 + threadIdx.y;
    if (seg >= nseg) return;
    int lane = threadIdx.x;
    float4 acc;
    if (add_smean) acc = ((const float4*)d_smean)[lane];
    else           acc = make_float4(0.f, 0.f, 0.f, 0.f);
    int b = off[seg], e = off[seg + 1];
    int t = b;
    for (; t + 4 <= e; t += 4) {
        int2 e0 = ei[t], e1 = ei[t + 1], e2 = ei[t + 2], e3 = ei[t + 3];
        float4 x0 = src[(size_t)e0.x * 32 + lane];
        float4 x1 = src[(size_t)e1.x * 32 + lane];
        float4 x2 = src[(size_t)e2.x * 32 + lane];
        float4 x3 = src[(size_t)e3.x * 32 + lane];
        float v0 = __int_as_float(e0.y), v1 = __int_as_float(e1.y);
        float v2 = __int_as_float(e2.y), v3 = __int_as_float(e3.y);
        acc.x += x0.x * v0 + x1.x * v1 + x2.x * v2 + x3.x * v3;
        acc.y += x0.y * v0 + x1.y * v1 + x2.y * v2 + x3.y * v3;
        acc.z += x0.z * v0 + x1.z * v1 + x2.z * v2 + x3.z * v3;
        acc.w += x0.w * v0 + x1.w * v1 + x2.w * v2 + x3.w * v3;
    }
    for (; t < e; t++) {
        int2 e0 = ei[t];
        float v0 = __int_as_float(e0.y);
        float4 x0 = src[(size_t)e0.x * 32 + lane];
        acc.x += x0.x * v0; acc.y += x0.y * v0;
        acc.z += x0.z * v0; acc.w += x0.w * v0;
    }
    dst[(size_t)seg * 32 + lane] = acc;
}

// ---------------- weight prep: fp32 -> tf32, permuted rows ----------------
__device__ __forceinline__ uint32_t f2tf32(float f) {
    uint32_t u;
    asm("cvt.rna.tf32.f32 %0, %1;" : "=r"(u) : "f"(f));
    return u;
}

__global__ void k_wprep(const float* __restrict__ Wih, const float* __restrict__ Whh) {
    int j = blockIdx.x;
    int k = threadIdx.x;
    int w = j / 96, rem = j % 96;
    int part = rem / 32, idx = rem % 32;
    int srow = part * 128 + w * 32 + idx;
    d_wtih[j * 128 + k] = f2tf32(Wih[srow * 128 + k]);
    d_wthh[j * 128 + k] = f2tf32(Whh[srow * 128 + k]);
}

// ---------------- fused GRU: gx=msg@Wih^T, gh=h@Whh^T, gate, h update ----------------
__device__ __forceinline__ float sigmf(float x) { return 1.f / (1.f + expf(-x)); }

#define MMA_TF32(acc, a0, a1, a2, a3, b0, b1)                               \
    asm volatile("mma.sync.aligned.m16n8k8.row.col.f32.tf32.tf32.f32 "      \
                 "{%0,%1,%2,%3}, {%4,%5,%6,%7}, {%8,%9}, {%0,%1,%2,%3};"    \
                 : "+f"(acc[0]), "+f"(acc[1]), "+f"(acc[2]), "+f"(acc[3])   \
                 : "r"(a0), "r"(a1), "r"(a2), "r"(a3), "r"(b0), "r"(b1));

#define SMEM_U32 29952

__global__ void __launch_bounds__(256, 1)
k_gru_fused(const float* __restrict__ msg, const float* __restrict__ h_in,
            float* __restrict__ h_out,
            const float* __restrict__ bih, const float* __restrict__ bhh, int M) {
    extern __shared__ uint32_t su[];
    uint32_t* sAx = su;
    uint32_t* sAh = su + 1152;
    uint32_t* sBi = su + 2304;
    uint32_t* sBh = su + 16128;

    int tid = threadIdx.x;
    int lane = tid & 31;
    int wid = tid >> 5;
    int rowHalf = wid >> 2;
    int cg = wid & 3;
    int mr = rowHalf * 16;
    int nb = cg * 96;
    int m0 = blockIdx.x * 32;

    float accX[12][4], accH[12][4];
    #pragma unroll
    for (int t = 0; t < 12; t++)
        #pragma unroll
        for (int i = 0; i < 4; i++) { accX[t][i] = 0.f; accH[t][i] = 0.f; }

    const float4* msg4 = (const float4*)msg;
    const float4* h4   = (const float4*)h_in;
    const uint4*  wi4  = (const uint4*)d_wtih;
    const uint4*  wh4  = (const uint4*)d_wthh;

    for (int kc = 0; kc < 4; kc++) {
        #pragma unroll
        for (int i = 0; i < 2; i++) {
            int id = tid + i * 256;
            int mtx = id >> 8;
            int r = (id >> 3) & 31;
            int f4 = id & 7;
            float4 v = make_float4(0.f, 0.f, 0.f, 0.f);
            int grow = m0 + r;
            if (grow < M)
                v = (mtx ? h4 : msg4)[(size_t)grow * 32 + kc * 8 + f4];
            uint4 o;
            o.x = f2tf32(v.x); o.y = f2tf32(v.y);
            o.z = f2tf32(v.z); o.w = f2tf32(v.w);
            uint32_t* dst = mtx ? sAh : sAx;
            *(uint4*)(dst + r * 36 + f4 * 4) = o;
        }
        #pragma unroll
        for (int i = 0; i < 24; i++) {
            int id = tid + i * 256;
            int q = id >> 3;
            int mtx = (q >= 384) ? 1 : 0;
            int r = q - mtx * 384;
            int f4 = id & 7;
            uint4 v = (mtx ? wh4 : wi4)[r * 32 + kc * 8 + f4];
            uint32_t* dst = mtx ? sBh : sBi;
            *(uint4*)(dst + r * 36 + f4 * 4) = v;
        }
        __syncthreads();

        #pragma unroll
        for (int kt = 0; kt < 4; kt++) {
            int k1 = kt * 8 + (lane & 3);
            int ar = (mr + (lane >> 2)) * 36 + k1;
            uint32_t ax0 = sAx[ar],       ax1 = sAx[ar + 8 * 36];
            uint32_t ax2 = sAx[ar + 4],   ax3 = sAx[ar + 8 * 36 + 4];
            uint32_t ah0 = sAh[ar],       ah1 = sAh[ar + 8 * 36];
            uint32_t ah2 = sAh[ar + 4],   ah3 = sAh[ar + 8 * 36 + 4];
            #pragma unroll
            for (int t = 0; t < 12; t++) {
                int br = (nb + t * 8 + (lane >> 2)) * 36 + k1;
                uint32_t bi0 = sBi[br], bi1 = sBi[br + 4];
                uint32_t bh0 = sBh[br], bh1 = sBh[br + 4];
                MMA_TF32(accX[t], ax0, ax1, ax2, ax3, bi0, bi1);
                MMA_TF32(accH[t], ah0, ah1, ah2, ah3, bh0, bh1);
            }
        }
        __syncthreads();
    }

    int c2 = (lane & 3) * 2;
    int r0 = m0 + mr + (lane >> 2);
    #pragma unroll
    for (int t2 = 0; t2 < 4; t2++) {
        #pragma unroll
        for (int half = 0; half < 2; half++) {
            int g = cg * 32 + t2 * 8 + c2 + half;
            float bir = bih[g] + bhh[g];
            float biz = bih[128 + g] + bhh[128 + g];
            float bin_ = bih[256 + g];
            float bhn = bhh[256 + g];
            #pragma unroll
            for (int rr = 0; rr < 2; rr++) {
                int row = r0 + rr * 8;
                if (row >= M) continue;
                int ci = rr * 2 + half;
                float r = sigmf(accX[t2][ci] + accH[t2][ci] + bir);
                float z = sigmf(accX[t2 + 4][ci] + accH[t2 + 4][ci] + biz);
                float nn = tanhf(accX[t2 + 8][ci] + bin_ + r * (accH[t2 + 8][ci] + bhn));
                float ho = h_in[(size_t)row * 128 + g];
                h_out[(size_t)row * 128 + g] = (1.f - z) * nn + z * ho;
            }
        }
    }
}

// ---------------- final FC: 64 rows/block, 8 rows/warp, dynamic smem ----------------
// layout: Wt (128*33 floats) then rowbuf (64*128 floats)
#define FC_SMEM_FLOATS (128 * 33 + 64 * 128)

__global__ void __launch_bounds__(256)
k_fc(const float* __restrict__ es, const float* __restrict__ fcw,
     const float* __restrict__ fcb, float* __restrict__ logits) {
    extern __shared__ float sf[];
    float* Wt = sf;                    // [128][33]
    float* rowbuf = sf + 128 * 33;     // [64][128]
    int tid = threadIdx.x;
    #pragma unroll
    for (int i = 0; i < 4; i++) {
        int idx = tid + i * 256;          // [32 j][32 k4]
        int j = idx >> 5, k4 = idx & 31;
        float4 w = ((const float4*)fcw)[j * 32 + k4];
        Wt[(k4 * 4 + 0) * 33 + j] = w.x; Wt[(k4 * 4 + 1) * 33 + j] = w.y;
        Wt[(k4 * 4 + 2) * 33 + j] = w.z; Wt[(k4 * 4 + 3) * 33 + j] = w.w;
    }
    int base = blockIdx.x * 64;
    #pragma unroll
    for (int i = 0; i < 8; i++) {
        int id = tid + i * 256;           // [0,2048) float4s
        int r = id >> 5, f4 = id & 31;
        ((float4*)(rowbuf + r * 128))[f4] =
            ((const float4*)(es + (size_t)(base + r) * 128))[f4];
    }
    __syncthreads();
    int w = tid >> 5, lane = tid & 31;
    float acc[8];
    float b = fcb[lane];
    #pragma unroll
    for (int r = 0; r < 8; r++) acc[r] = b;
    for (int k = 0; k < 128; k++) {
        float wt = Wt[k * 33 + lane];
        #pragma unroll
        for (int r = 0; r < 8; r++)
            acc[r] += rowbuf[(w * 8 + r) * 128 + k] * wt;
    }
    #pragma unroll
    for (int r = 0; r < 8; r++)
        logits[(size_t)(base + w * 8 + r) * Cn + lane] = acc[r];
}

// ---------------- host orchestration ----------------
extern "C" void kernel_launch(void* const* d_in, const int* in_sizes, int n_in,
                              void* d_out, int out_size) {
    (void)in_sizes; (void)n_in; (void)out_size;
    const int*   seed_index = (const int*)d_in[0];
    const float* es_in  = (const float*)d_in[1];
    const float* ps_in  = (const float*)d_in[2];
    const int*   rows   = (const int*)d_in[3];
    const int*   cols   = (const int*)d_in[4];
    const float* vals   = (const float*)d_in[5];
    const float* fcw    = (const float*)d_in[22];
    const float* fcb    = (const float*)d_in[23];

    float* out       = (float*)d_out;
    float* out_logit = out;
    float* out_es    = out + (size_t)En * Cn;
    float* out_ps    = out_es + (size_t)En * Dn;

    cudaFuncSetAttribute(k_gru_fused, cudaFuncAttributeMaxDynamicSharedMemorySize,
                         SMEM_U32 * 4);
    cudaFuncSetAttribute(k_fc, cudaFuncAttributeMaxDynamicSharedMemorySize,
                         FC_SMEM_FLOATS * 4);

    void *pOffP, *pOffE, *pEiP, *pEiE, *pPmsg, *pEmsg;
    cudaGetSymbolAddress(&pOffP, d_offP);
    cudaGetSymbolAddress(&pOffE, d_offE);
    cudaGetSymbolAddress(&pEiP, d_eiP);
    cudaGetSymbolAddress(&pEiE, d_eiE);
    cudaGetSymbolAddress(&pPmsg, d_pmsg);
    cudaGetSymbolAddress(&pEmsg, d_emsg);

    // CSR build (both directions), fused scans
    k_zero_counts<<<(En + 255) / 256, 256>>>();
    k_count<<<(NNZn + 255) / 256, 256>>>(rows, cols);
    k_scan1<<<NBP + NBE, 1024>>>();
    k_scan2<<<2, 1024>>>();
    k_scan3<<<NBP + NBE, 1024>>>();
    k_fill<<<(NNZn + 255) / 256, 256>>>(rows, cols, vals);

    dim3 spmmB(32, 8);
    size_t smemB = SMEM_U32 * 4;

    for (int l = 0; l < 2; l++) {
        const float* eWih = (const float*)d_in[6 + l * 8 + 0];
        const float* eWhh = (const float*)d_in[6 + l * 8 + 1];
        const float* ebih = (const float*)d_in[6 + l * 8 + 2];
        const float* ebhh = (const float*)d_in[6 + l * 8 + 3];
        const float* pWih = (const float*)d_in[6 + l * 8 + 4];
        const float* pWhh = (const float*)d_in[6 + l * 8 + 5];
        const float* pbih = (const float*)d_in[6 + l * 8 + 6];
        const float* pbhh = (const float*)d_in[6 + l * 8 + 7];

        const float* es_cur = (l == 0) ? es_in : out_es;
        const float* ps_cur = (l == 0) ? ps_in : out_ps;

        k_seed_mean<<<1, dim3(128, 8)>>>(es_cur, seed_index);

        // p_msg = segment_sum(es[row]*w, col); ps = GRU(p_msg, ps)
        k_spmm<<<(Pn + 7) / 8, spmmB>>>((const float4*)es_cur, (float4*)pPmsg,
                                        (const int*)pOffP, (const int2*)pEiP, Pn, 0);
        k_wprep<<<G3, 128>>>(pWih, pWhh);
        k_gru_fused<<<(Pn + 31) / 32, 256, smemB>>>((const float*)pPmsg, ps_cur,
                                                    out_ps, pbih, pbhh, Pn);

        // e_msg = segment_sum(ps[col]*w, row) + seed_mean; es = GRU(e_msg, es)
        k_spmm<<<(En + 7) / 8, spmmB>>>((const float4*)out_ps, (float4*)pEmsg,
                                        (const int*)pOffE, (const int2*)pEiE, En, 1);
        k_wprep<<<G3, 128>>>(eWih, eWhh);
        k_gru_fused<<<(En + 31) / 32, 256, smemB>>>((const float*)pEmsg, es_cur,
                                                    out_es, ebih, ebhh, En);
    }

    k_fc<<<En / 64, 256, FC_SMEM_FLOATS * 4>>>(out_es, fcw, fcb, out_logit);
}

// round 7
// speedup vs baseline: 1.4997x; 1.1298x over previous
#include <cuda_runtime.h>
#include <math.h>
#include <stdint.h>

#define En     200000
#define Pn     50000
#define Dn     128
#define NNZn   2000000
#define Cn     32
#define NSEEDn 320
#define G3     384   // 3*D

// ---------------- scratch (device globals; no allocation allowed) ----------------
__device__ float d_pmsg[(size_t)Pn * Dn];
__device__ float d_emsg[(size_t)En * Dn];
__device__ int   d_cntP[Pn];
__device__ int   d_offP[Pn + 1];
__device__ int   d_curP[Pn];
__device__ int   d_cntE[En];
__device__ int   d_offE[En + 1];
__device__ int   d_curE[En];
__device__ int2  d_eiP[NNZn];          // (src_row, val_bits)
__device__ int2  d_eiE[NNZn];          // (src_col, val_bits)
__device__ float d_smean[Dn];
__device__ int   d_partP[64];
__device__ int   d_partE[256];
// cat weights, tf32: rows 0..383 = [Wih | Whh]; rows 384..511 = [0 | Whh_n]
__device__ uint32_t d_wcat2[512 * 256];

#define NBP ((Pn + 1023) / 1024)   // 49
#define NBE ((En + 1023) / 1024)   // 196

// ---------------- helpers ----------------
__device__ __forceinline__ uint32_t smem_u32(const void* p) {
    uint32_t a;
    asm("{ .reg .u64 t; cvta.to.shared.u64 t, %1; cvt.u32.u64 %0, t; }" : "=r"(a) : "l"(p));
    return a;
}
__device__ __forceinline__ uint32_t f2tf32(float f) {
    uint32_t u;
    asm("cvt.rna.tf32.f32 %0, %1;" : "=r"(u) : "f"(f));
    return u;
}
__device__ __forceinline__ float sigmf(float x) { return 1.f / (1.f + expf(-x)); }

#define MMA_TF32(acc, a0, a1, a2, a3, b0, b1)                               \
    asm volatile("mma.sync.aligned.m16n8k8.row.col.f32.tf32.tf32.f32 "      \
                 "{%0,%1,%2,%3}, {%4,%5,%6,%7}, {%8,%9}, {%0,%1,%2,%3};"    \
                 : "+f"(acc[0]), "+f"(acc[1]), "+f"(acc[2]), "+f"(acc[3])   \
                 : "r"(a0), "r"(a1), "r"(a2), "r"(a3), "r"(b0), "r"(b1));

// ---------------- CSR build ----------------
__global__ void k_zero_counts() {
    int i = blockIdx.x * blockDim.x + threadIdx.x;
    if (i < En) d_cntE[i] = 0;
    if (i < Pn) d_cntP[i] = 0;
}

__global__ void k_count(const int* __restrict__ rows, const int* __restrict__ cols) {
    int i = blockIdx.x * blockDim.x + threadIdx.x;
    if (i < NNZn) {
        atomicAdd(&d_cntE[rows[i]], 1);
        atomicAdd(&d_cntP[cols[i]], 1);
    }
}

__global__ void k_scan1() {
    __shared__ int s[1024];
    int isE = (blockIdx.x >= NBP);
    int b = isE ? blockIdx.x - NBP : blockIdx.x;
    const int* cnt = isE ? d_cntE : d_cntP;
    int* off = isE ? d_offE : d_offP;
    int* part = isE ? d_partE : d_partP;
    int n = isE ? En : Pn;
    int g = b * 1024 + threadIdx.x;
    s[threadIdx.x] = (g < n) ? cnt[g] : 0;
    __syncthreads();
    for (int o = 1; o < 1024; o <<= 1) {
        int t = (threadIdx.x >= o) ? s[threadIdx.x - o] : 0;
        __syncthreads();
        s[threadIdx.x] += t;
        __syncthreads();
    }
    if (g < n) off[g + 1] = s[threadIdx.x];
    if (threadIdx.x == 1023) part[b] = s[1023];
    if (g == 0) off[0] = 0;
}

__global__ void k_scan2() {
    __shared__ int s[1024];
    int isE = (blockIdx.x == 1);
    int* part = isE ? d_partE : d_partP;
    int n = isE ? NBE : NBP;
    s[threadIdx.x] = (threadIdx.x < n) ? part[threadIdx.x] : 0;
    __syncthreads();
    for (int o = 1; o < 1024; o <<= 1) {
        int t = (threadIdx.x >= o) ? s[threadIdx.x - o] : 0;
        __syncthreads();
        s[threadIdx.x] += t;
        __syncthreads();
    }
    if (threadIdx.x < n)
        part[threadIdx.x] = (threadIdx.x == 0) ? 0 : s[threadIdx.x - 1];
}

__global__ void k_scan3() {
    int isE = (blockIdx.x >= NBP);
    int b = isE ? blockIdx.x - NBP : blockIdx.x;
    int* off = isE ? d_offE : d_offP;
    int* cur = isE ? d_curE : d_curP;
    const int* part = isE ? d_partE : d_partP;
    int n = isE ? En : Pn;
    int g = b * 1024 + threadIdx.x;
    if (g < n) {
        int v = off[g + 1] + part[b];
        off[g + 1] = v;
        if (g + 1 < n) cur[g + 1] = v;
    }
    if (g == 0) cur[0] = 0;
}

__global__ void k_fill(const int* __restrict__ rows, const int* __restrict__ cols,
                       const float* __restrict__ vals) {
    int i = blockIdx.x * blockDim.x + threadIdx.x;
    if (i < NNZn) {
        int r = rows[i], c = cols[i];
        int vb = __float_as_int(vals[i]);
        int pp = atomicAdd(&d_curP[c], 1);
        d_eiP[pp] = make_int2(r, vb);
        int pe = atomicAdd(&d_curE[r], 1);
        d_eiE[pe] = make_int2(c, vb);
    }
}

// ---------------- seed mean ----------------
__global__ void k_seed_mean(const float* __restrict__ es, const int* __restrict__ sidx) {
    __shared__ float red[8][128];
    int d = threadIdx.x, ty = threadIdx.y;
    float s = 0.f;
    for (int i = ty; i < NSEEDn; i += 8)
        s += es[(size_t)sidx[i] * Dn + d];
    red[ty][d] = s;
    __syncthreads();
    if (ty == 0) {
        float tot = 0.f;
        #pragma unroll
        for (int j = 0; j < 8; j++) tot += red[j][d];
        d_smean[d] = tot * (1.f / NSEEDn);
    }
}

// ---------------- SpMM: one warp per segment ----------------
__global__ void k_spmm(const float4* __restrict__ src, float4* __restrict__ dst,
                       const int* __restrict__ off, const int2* __restrict__ ei,
                       int nseg, int add_smean) {
    int seg = blockIdx.x * 8 + threadIdx.y;
    if (seg >= nseg) return;
    int lane = threadIdx.x;
    float4 acc;
    if (add_smean) acc = ((const float4*)d_smean)[lane];
    else           acc = make_float4(0.f, 0.f, 0.f, 0.f);
    int b = off[seg], e = off[seg + 1];
    int t = b;
    for (; t + 4 <= e; t += 4) {
        int2 e0 = ei[t], e1 = ei[t + 1], e2 = ei[t + 2], e3 = ei[t + 3];
        float4 x0 = src[(size_t)e0.x * 32 + lane];
        float4 x1 = src[(size_t)e1.x * 32 + lane];
        float4 x2 = src[(size_t)e2.x * 32 + lane];
        float4 x3 = src[(size_t)e3.x * 32 + lane];
        float v0 = __int_as_float(e0.y), v1 = __int_as_float(e1.y);
        float v2 = __int_as_float(e2.y), v3 = __int_as_float(e3.y);
        acc.x += x0.x * v0 + x1.x * v1 + x2.x * v2 + x3.x * v3;
        acc.y += x0.y * v0 + x1.y * v1 + x2.y * v2 + x3.y * v3;
        acc.z += x0.z * v0 + x1.z * v1 + x2.z * v2 + x3.z * v3;
        acc.w += x0.w * v0 + x1.w * v1 + x2.w * v2 + x3.w * v3;
    }
    for (; t < e; t++) {
        int2 e0 = ei[t];
        float v0 = __int_as_float(e0.y);
        float4 x0 = src[(size_t)e0.x * 32 + lane];
        acc.x += x0.x * v0; acc.y += x0.y * v0;
        acc.z += x0.z * v0; acc.w += x0.w * v0;
    }
    dst[(size_t)seg * 32 + lane] = acc;
}

// ---------------- weight prep: cat matrix [512][256] tf32 ----------------
__global__ void k_wprep2(const float* __restrict__ Wih, const float* __restrict__ Whh) {
    int n = blockIdx.x;      // 0..511
    int k = threadIdx.x;     // 0..255
    float v;
    if (n < 384) v = (k < 128) ? Wih[n * 128 + k] : Whh[n * 128 + (k - 128)];
    else         v = (k < 128) ? 0.f : Whh[(256 + (n - 384)) * 128 + (k - 128)];
    d_wcat2[n * 256 + k] = f2tf32(v);
}

// ---------------- GRU: cat-GEMM, M=64/block, double-buffered cp.async ----------------
// Buffer (u32 units): A 64*36=2304, B 512*36=18432 -> 20736 per buffer, x2.
#define GRU2_BUF_U32 20736
#define GRU2_SMEM    (2 * GRU2_BUF_U32 * 4)   // 165888 bytes

__device__ __forceinline__ void gru2_loadA(uint32_t sbase, int bsel,
        const float4* msg4, const float4* h4, int c, int m0, int M, int tid) {
    int r = tid >> 3, j = tid & 7;
    const float4* s4 = (c < 4) ? msg4 : h4;
    int koff = (c & 3) * 8;
    float4 v = make_float4(0.f, 0.f, 0.f, 0.f);
    int grow = m0 + r;
    if (grow < M) v = s4[(size_t)grow * 32 + koff + j];
    uint32_t o0 = f2tf32(v.x), o1 = f2tf32(v.y), o2 = f2tf32(v.z), o3 = f2tf32(v.w);
    uint32_t dst = sbase + (uint32_t)(bsel * GRU2_BUF_U32 + r * 36 + j * 4) * 4;
    asm volatile("st.shared.v4.b32 [%0], {%1,%2,%3,%4};"
                 :: "r"(dst), "r"(o0), "r"(o1), "r"(o2), "r"(o3));
}

__device__ __forceinline__ void gru2_loadB(uint32_t sbase, int bsel,
        const float4* w4, int c, int tid) {
    #pragma unroll
    for (int i = 0; i < 8; i++) {
        int id = tid + i * 512;
        int r = id >> 3, j = id & 7;
        if (c >= 4 || r < 384) {   // rows 384..511 are zero for k<128; skipped
            uint32_t dst = sbase + (uint32_t)(bsel * GRU2_BUF_U32 + 2304 + r * 36 + j * 4) * 4;
            const float4* src = w4 + (size_t)r * 64 + c * 8 + j;
            asm volatile("cp.async.cg.shared.global [%0], [%1], 16;"
                         :: "r"(dst), "l"(src) : "memory");
        }
    }
    asm volatile("cp.async.commit_group;" ::: "memory");
}

__device__ __forceinline__ void gru2_compute(const uint32_t* dyn, int bsel,
        int rg, int cg, int lane, float acc[16][4]) {
    const uint32_t* A = dyn + bsel * GRU2_BUF_U32;
    const uint32_t* B = A + 2304;
    #pragma unroll
    for (int kt = 0; kt < 4; kt++) {
        int k1 = kt * 8 + (lane & 3);
        int ar = (rg * 16 + (lane >> 2)) * 36 + k1;
        uint32_t a0 = A[ar], a1 = A[ar + 8 * 36];
        uint32_t a2 = A[ar + 4], a3 = A[ar + 8 * 36 + 4];
        #pragma unroll
        for (int t = 0; t < 16; t++) {
            int br = (cg * 128 + t * 8 + (lane >> 2)) * 36 + k1;
            uint32_t b0 = B[br], b1 = B[br + 4];
            MMA_TF32(acc[t], a0, a1, a2, a3, b0, b1);
        }
    }
}

__global__ void __launch_bounds__(512, 1)
k_gru2(const float* __restrict__ msg, const float* __restrict__ h_in,
       float* __restrict__ h_out, const float* __restrict__ bih,
       const float* __restrict__ bhh, int M) {
    extern __shared__ uint32_t dyn[];
    int tid = threadIdx.x;
    int lane = tid & 31, wid = tid >> 5;
    int cg = wid >> 2;       // col group: 128 cat-cols (3=Hn)
    int rg = wid & 3;        // row group: 16 rows
    int m0 = blockIdx.x * 64;
    uint32_t sbase = smem_u32(dyn);

    const float4* msg4 = (const float4*)msg;
    const float4* h4   = (const float4*)h_in;
    const float4* w4   = (const float4*)d_wcat2;

    float acc[16][4];
    #pragma unroll
    for (int t = 0; t < 16; t++)
        #pragma unroll
        for (int i = 0; i < 4; i++) acc[t][i] = 0.f;

    gru2_loadA(sbase, 0, msg4, h4, 0, m0, M, tid);
    gru2_loadB(sbase, 0, w4, 0, tid);

    for (int c = 0; c < 8; c++) {
        if (c < 7) {
            gru2_loadA(sbase, (c + 1) & 1, msg4, h4, c + 1, m0, M, tid);
            gru2_loadB(sbase, (c + 1) & 1, w4, c + 1, tid);
            asm volatile("cp.async.wait_group 1;" ::: "memory");
        } else {
            asm volatile("cp.async.wait_group 0;" ::: "memory");
        }
        __syncthreads();
        if (cg < 3 || c >= 4)
            gru2_compute(dyn, c & 1, rg, cg, lane, acc);
        __syncthreads();
    }

    // write S to smem: [64][516] floats (reuses pipeline buffers)
    float* S = (float*)dyn;
    #pragma unroll
    for (int t = 0; t < 16; t++) {
        int n0 = cg * 128 + t * 8 + (lane & 3) * 2;
        int rb = rg * 16 + (lane >> 2);
        S[rb * 516 + n0]       = acc[t][0];
        S[rb * 516 + n0 + 1]   = acc[t][1];
        S[(rb + 8) * 516 + n0]     = acc[t][2];
        S[(rb + 8) * 516 + n0 + 1] = acc[t][3];
    }
    __syncthreads();

    // gate: 8 threads/row, 16 cols each (4x float4)
    int r = tid >> 3;
    int row = m0 + r;
    if (row < M) {
        const float4* bi4 = (const float4*)bih;
        const float4* bh4 = (const float4*)bhh;
        #pragma unroll
        for (int q = 0; q < 4; q++) {
            int g4 = (tid & 7) * 4 + q;          // 0..31
            float4 Sr = *(const float4*)(S + r * 516 + g4 * 4);
            float4 Sz = *(const float4*)(S + r * 516 + 128 + g4 * 4);
            float4 Sn = *(const float4*)(S + r * 516 + 256 + g4 * 4);
            float4 Hn = *(const float4*)(S + r * 516 + 384 + g4 * 4);
            float4 bir = bi4[g4], biz = bi4[32 + g4], bin_ = bi4[64 + g4];
            float4 bhr = bh4[g4], bhz = bh4[32 + g4], bhn = bh4[64 + g4];
            float4 hv = ((const float4*)h_in)[(size_t)row * 32 + g4];
            float4 o;
#define GG(cmp) { \
            float rr_ = sigmf(Sr.cmp + bir.cmp + bhr.cmp); \
            float zz_ = sigmf(Sz.cmp + biz.cmp + bhz.cmp); \
            float xn_ = Sn.cmp - Hn.cmp; \
            float nn_ = tanhf(xn_ + bin_.cmp + rr_ * (Hn.cmp + bhn.cmp)); \
            o.cmp = (1.f - zz_) * nn_ + zz_ * hv.cmp; }
            GG(x) GG(y) GG(z) GG(w)
#undef GG
            ((float4*)h_out)[(size_t)row * 32 + g4] = o;
        }
    }
}

// ---------------- final FC: 64 rows/block, dynamic smem ----------------
#define FC_SMEM_FLOATS (128 * 33 + 64 * 128)

__global__ void __launch_bounds__(256)
k_fc(const float* __restrict__ es, const float* __restrict__ fcw,
     const float* __restrict__ fcb, float* __restrict__ logits) {
    extern __shared__ float sf[];
    float* Wt = sf;                    // [128][33]
    float* rowbuf = sf + 128 * 33;     // [64][128]
    int tid = threadIdx.x;
    #pragma unroll
    for (int i = 0; i < 4; i++) {
        int idx = tid + i * 256;
        int j = idx >> 5, k4 = idx & 31;
        float4 w = ((const float4*)fcw)[j * 32 + k4];
        Wt[(k4 * 4 + 0) * 33 + j] = w.x; Wt[(k4 * 4 + 1) * 33 + j] = w.y;
        Wt[(k4 * 4 + 2) * 33 + j] = w.z; Wt[(k4 * 4 + 3) * 33 + j] = w.w;
    }
    int base = blockIdx.x * 64;
    #pragma unroll
    for (int i = 0; i < 8; i++) {
        int id = tid + i * 256;
        int r = id >> 5, f4 = id & 31;
        ((float4*)(rowbuf + r * 128))[f4] =
            ((const float4*)(es + (size_t)(base + r) * 128))[f4];
    }
    __syncthreads();
    int w = tid >> 5, lane = tid & 31;
    float acc[8];
    float b = fcb[lane];
    #pragma unroll
    for (int r = 0; r < 8; r++) acc[r] = b;
    for (int k = 0; k < 128; k++) {
        float wt = Wt[k * 33 + lane];
        #pragma unroll
        for (int r = 0; r < 8; r++)
            acc[r] += rowbuf[(w * 8 + r) * 128 + k] * wt;
    }
    #pragma unroll
    for (int r = 0; r < 8; r++)
        logits[(size_t)(base + w * 8 + r) * Cn + lane] = acc[r];
}

// ---------------- host orchestration ----------------
extern "C" void kernel_launch(void* const* d_in, const int* in_sizes, int n_in,
                              void* d_out, int out_size) {
    (void)in_sizes; (void)n_in; (void)out_size;
    const int*   seed_index = (const int*)d_in[0];
    const float* es_in  = (const float*)d_in[1];
    const float* ps_in  = (const float*)d_in[2];
    const int*   rows   = (const int*)d_in[3];
    const int*   cols   = (const int*)d_in[4];
    const float* vals   = (const float*)d_in[5];
    const float* fcw    = (const float*)d_in[22];
    const float* fcb    = (const float*)d_in[23];

    float* out       = (float*)d_out;
    float* out_logit = out;
    float* out_es    = out + (size_t)En * Cn;
    float* out_ps    = out_es + (size_t)En * Dn;

    cudaFuncSetAttribute(k_gru2, cudaFuncAttributeMaxDynamicSharedMemorySize, GRU2_SMEM);
    cudaFuncSetAttribute(k_fc, cudaFuncAttributeMaxDynamicSharedMemorySize,
                         FC_SMEM_FLOATS * 4);

    void *pOffP, *pOffE, *pEiP, *pEiE, *pPmsg, *pEmsg;
    cudaGetSymbolAddress(&pOffP, d_offP);
    cudaGetSymbolAddress(&pOffE, d_offE);
    cudaGetSymbolAddress(&pEiP, d_eiP);
    cudaGetSymbolAddress(&pEiE, d_eiE);
    cudaGetSymbolAddress(&pPmsg, d_pmsg);
    cudaGetSymbolAddress(&pEmsg, d_emsg);

    // CSR build
    k_zero_counts<<<(En + 255) / 256, 256>>>();
    k_count<<<(NNZn + 255) / 256, 256>>>(rows, cols);
    k_scan1<<<NBP + NBE, 1024>>>();
    k_scan2<<<2, 1024>>>();
    k_scan3<<<NBP + NBE, 1024>>>();
    k_fill<<<(NNZn + 255) / 256, 256>>>(rows, cols, vals);

    dim3 spmmB(32, 8);
    int gE = (En + 63) / 64;   // 3125
    int gP = (Pn + 63) / 64;   // 782

    for (int l = 0; l < 2; l++) {
        const float* eWih = (const float*)d_in[6 + l * 8 + 0];
        const float* eWhh = (const float*)d_in[6 + l * 8 + 1];
        const float* ebih = (const float*)d_in[6 + l * 8 + 2];
        const float* ebhh = (const float*)d_in[6 + l * 8 + 3];
        const float* pWih = (const float*)d_in[6 + l * 8 + 4];
        const float* pWhh = (const float*)d_in[6 + l * 8 + 5];
        const float* pbih = (const float*)d_in[6 + l * 8 + 6];
        const float* pbhh = (const float*)d_in[6 + l * 8 + 7];

        const float* es_cur = (l == 0) ? es_in : out_es;
        const float* ps_cur = (l == 0) ? ps_in : out_ps;

        k_seed_mean<<<1, dim3(128, 8)>>>(es_cur, seed_index);

        // p_msg = segment_sum(es[row]*w, col); ps = GRU(p_msg, ps)
        k_spmm<<<(Pn + 7) / 8, spmmB>>>((const float4*)es_cur, (float4*)pPmsg,
                                        (const int*)pOffP, (const int2*)pEiP, Pn, 0);
        k_wprep2<<<512, 256>>>(pWih, pWhh);
        k_gru2<<<gP, 512, GRU2_SMEM>>>((const float*)pPmsg, ps_cur, out_ps,
                                       pbih, pbhh, Pn);

        // e_msg = segment_sum(ps[col]*w, row) + seed_mean; es = GRU(e_msg, es)
        k_spmm<<<(En + 7) / 8, spmmB>>>((const float4*)out_ps, (float4*)pEmsg,
                                        (const int*)pOffE, (const int2*)pEiE, En, 1);
        k_wprep2<<<512, 256>>>(eWih, eWhh);
        k_gru2<<<gE, 512, GRU2_SMEM>>>((const float*)pEmsg, es_cur, out_es,
                                       ebih, ebhh, En);
    }

    k_fc<<<En / 64, 256, FC_SMEM_FLOATS * 4>>>(out_es, fcw, fcb, out_logit);
}

// round 8
// speedup vs baseline: 1.8024x; 1.2018x over previous
#include <cuda_runtime.h>
#include <cuda_fp16.h>
#include <math.h>
#include <stdint.h>

#define En     200000
#define Pn     50000
#define Dn     128
#define NNZn   2000000
#define Cn     32
#define NSEEDn 320
#define G3     384   // 3*D

// ---------------- scratch (device globals; no allocation allowed) ----------------
__device__ float d_pmsg[(size_t)Pn * Dn];
__device__ float d_emsg[(size_t)En * Dn];
__device__ int   d_cntP[Pn];
__device__ int   d_offP[Pn + 1];
__device__ int   d_curP[Pn];
__device__ int   d_cntE[En];
__device__ int   d_offE[En + 1];
__device__ int   d_curE[En];
__device__ int2  d_eiP[NNZn];          // (src_row, val_bits)
__device__ int2  d_eiE[NNZn];          // (src_col, val_bits)
__device__ float d_smean[Dn];
__device__ int   d_partP[64];
__device__ int   d_partE[256];
// fp16 cat weights, 4 slots (l0_p, l0_e, l1_p, l1_e):
// rows 0..383 = [Wih | Whh]; rows 384..511 = [0 | Whh_n]; 128 half2-pairs per row
__device__ uint32_t d_wcat2[4 * 512 * 128];

#define NBP ((Pn + 1023) / 1024)   // 49
#define NBE ((En + 1023) / 1024)   // 196

// ---------------- helpers ----------------
__device__ __forceinline__ uint32_t smem_u32(const void* p) {
    uint32_t a;
    asm("{ .reg .u64 t; cvta.to.shared.u64 t, %1; cvt.u32.u64 %0, t; }" : "=r"(a) : "l"(p));
    return a;
}
__device__ __forceinline__ float sigmf(float x) { return 1.f / (1.f + expf(-x)); }
__device__ __forceinline__ uint32_t pack_h2(float a, float b) {
    __half2 h = __floats2half2_rn(a, b);
    return *(uint32_t*)&h;
}

#define MMA_F16(acc, a0, a1, a2, a3, b0, b1)                                \
    asm volatile("mma.sync.aligned.m16n8k16.row.col.f32.f16.f16.f32 "       \
                 "{%0,%1,%2,%3}, {%4,%5,%6,%7}, {%8,%9}, {%0,%1,%2,%3};"    \
                 : "+f"(acc[0]), "+f"(acc[1]), "+f"(acc[2]), "+f"(acc[3])   \
                 : "r"(a0), "r"(a1), "r"(a2), "r"(a3), "r"(b0), "r"(b1));

// ---------------- CSR build ----------------
__global__ void k_zero_counts() {
    int i = blockIdx.x * blockDim.x + threadIdx.x;
    if (i < En) d_cntE[i] = 0;
    if (i < Pn) d_cntP[i] = 0;
}

__global__ void k_count(const int* __restrict__ rows, const int* __restrict__ cols) {
    int i = blockIdx.x * blockDim.x + threadIdx.x;
    if (i < NNZn) {
        atomicAdd(&d_cntE[rows[i]], 1);
        atomicAdd(&d_cntP[cols[i]], 1);
    }
}

__global__ void k_scan1() {
    __shared__ int s[1024];
    int isE = (blockIdx.x >= NBP);
    int b = isE ? blockIdx.x - NBP : blockIdx.x;
    const int* cnt = isE ? d_cntE : d_cntP;
    int* off = isE ? d_offE : d_offP;
    int* part = isE ? d_partE : d_partP;
    int n = isE ? En : Pn;
    int g = b * 1024 + threadIdx.x;
    s[threadIdx.x] = (g < n) ? cnt[g] : 0;
    __syncthreads();
    for (int o = 1; o < 1024; o <<= 1) {
        int t = (threadIdx.x >= o) ? s[threadIdx.x - o] : 0;
        __syncthreads();
        s[threadIdx.x] += t;
        __syncthreads();
    }
    if (g < n) off[g + 1] = s[threadIdx.x];
    if (threadIdx.x == 1023) part[b] = s[1023];
    if (g == 0) off[0] = 0;
}

__global__ void k_scan2() {
    __shared__ int s[1024];
    int isE = (blockIdx.x == 1);
    int* part = isE ? d_partE : d_partP;
    int n = isE ? NBE : NBP;
    s[threadIdx.x] = (threadIdx.x < n) ? part[threadIdx.x] : 0;
    __syncthreads();
    for (int o = 1; o < 1024; o <<= 1) {
        int t = (threadIdx.x >= o) ? s[threadIdx.x - o] : 0;
        __syncthreads();
        s[threadIdx.x] += t;
        __syncthreads();
    }
    if (threadIdx.x < n)
        part[threadIdx.x] = (threadIdx.x == 0) ? 0 : s[threadIdx.x - 1];
}

__global__ void k_scan3() {
    int isE = (blockIdx.x >= NBP);
    int b = isE ? blockIdx.x - NBP : blockIdx.x;
    int* off = isE ? d_offE : d_offP;
    int* cur = isE ? d_curE : d_curP;
    const int* part = isE ? d_partE : d_partP;
    int n = isE ? En : Pn;
    int g = b * 1024 + threadIdx.x;
    if (g < n) {
        int v = off[g + 1] + part[b];
        off[g + 1] = v;
        if (g + 1 < n) cur[g + 1] = v;
    }
    if (g == 0) cur[0] = 0;
}

__global__ void k_fill(const int* __restrict__ rows, const int* __restrict__ cols,
                       const float* __restrict__ vals) {
    int i = blockIdx.x * blockDim.x + threadIdx.x;
    if (i < NNZn) {
        int r = rows[i], c = cols[i];
        int vb = __float_as_int(vals[i]);
        int pp = atomicAdd(&d_curP[c], 1);
        d_eiP[pp] = make_int2(r, vb);
        int pe = atomicAdd(&d_curE[r], 1);
        d_eiE[pe] = make_int2(c, vb);
    }
}

// ---------------- seed mean ----------------
__global__ void k_seed_mean(const float* __restrict__ es, const int* __restrict__ sidx) {
    __shared__ float red[8][128];
    int d = threadIdx.x, ty = threadIdx.y;
    float s = 0.f;
    for (int i = ty; i < NSEEDn; i += 8)
        s += es[(size_t)sidx[i] * Dn + d];
    red[ty][d] = s;
    __syncthreads();
    if (ty == 0) {
        float tot = 0.f;
        #pragma unroll
        for (int j = 0; j < 8; j++) tot += red[j][d];
        d_smean[d] = tot * (1.f / NSEEDn);
    }
}

// ---------------- SpMM: one warp per segment ----------------
__global__ void k_spmm(const float4* __restrict__ src, float4* __restrict__ dst,
                       const int* __restrict__ off, const int2* __restrict__ ei,
                       int nseg, int add_smean) {
    int seg = blockIdx.x * 8 + threadIdx.y;
    if (seg >= nseg) return;
    int lane = threadIdx.x;
    float4 acc;
    if (add_smean) acc = ((const float4*)d_smean)[lane];
    else           acc = make_float4(0.f, 0.f, 0.f, 0.f);
    int b = off[seg], e = off[seg + 1];
    int t = b;
    for (; t + 4 <= e; t += 4) {
        int2 e0 = ei[t], e1 = ei[t + 1], e2 = ei[t + 2], e3 = ei[t + 3];
        float4 x0 = src[(size_t)e0.x * 32 + lane];
        float4 x1 = src[(size_t)e1.x * 32 + lane];
        float4 x2 = src[(size_t)e2.x * 32 + lane];
        float4 x3 = src[(size_t)e3.x * 32 + lane];
        float v0 = __int_as_float(e0.y), v1 = __int_as_float(e1.y);
        float v2 = __int_as_float(e2.y), v3 = __int_as_float(e3.y);
        acc.x += x0.x * v0 + x1.x * v1 + x2.x * v2 + x3.x * v3;
        acc.y += x0.y * v0 + x1.y * v1 + x2.y * v2 + x3.y * v3;
        acc.z += x0.z * v0 + x1.z * v1 + x2.z * v2 + x3.z * v3;
        acc.w += x0.w * v0 + x1.w * v1 + x2.w * v2 + x3.w * v3;
    }
    for (; t < e; t++) {
        int2 e0 = ei[t];
        float v0 = __int_as_float(e0.y);
        float4 x0 = src[(size_t)e0.x * 32 + lane];
        acc.x += x0.x * v0; acc.y += x0.y * v0;
        acc.z += x0.z * v0; acc.w += x0.w * v0;
    }
    dst[(size_t)seg * 32 + lane] = acc;
}

// ---------------- weight prep: all 4 GRU cat matrices, fp16 ----------------
__global__ void k_wprep_all(
    const float* __restrict__ p0ih, const float* __restrict__ p0hh,
    const float* __restrict__ e0ih, const float* __restrict__ e0hh,
    const float* __restrict__ p1ih, const float* __restrict__ p1hh,
    const float* __restrict__ e1ih, const float* __restrict__ e1hh) {
    int slot = blockIdx.x >> 9;       // 0..3
    int n = blockIdx.x & 511;         // 0..511
    int p = threadIdx.x;              // pair 0..127
    const float* Wih;
    const float* Whh;
    switch (slot) {
        case 0: Wih = p0ih; Whh = p0hh; break;
        case 1: Wih = e0ih; Whh = e0hh; break;
        case 2: Wih = p1ih; Whh = p1hh; break;
        default: Wih = e1ih; Whh = e1hh; break;
    }
    float v0, v1;
    int k0 = 2 * p, k1 = 2 * p + 1;
    if (n < 384) {
        v0 = (k0 < 128) ? Wih[n * 128 + k0] : Whh[n * 128 + (k0 - 128)];
        v1 = (k1 < 128) ? Wih[n * 128 + k1] : Whh[n * 128 + (k1 - 128)];
    } else {
        int nn = 256 + (n - 384);
        v0 = (k0 < 128) ? 0.f : Whh[nn * 128 + (k0 - 128)];
        v1 = (k1 < 128) ? 0.f : Whh[nn * 128 + (k1 - 128)];
    }
    d_wcat2[slot * 65536 + n * 128 + p] = pack_h2(v0, v1);
}

// ---------------- GRU: fp16 cat-GEMM, M=64/block, double-buffered cp.async ----------------
// Per buffer (u32): A 64*20=1280 (16 pairs used), B 512*20=10240 -> 11520; x2 = 92160 B
// Epilogue S: [64][516] floats = 132096 B (reuses pipeline region; smem sized to max)
#define GRU2_BUF_U32 11520
#define GRU2_SMEM    132096

__device__ __forceinline__ void gru2_loadA(uint32_t sbase, int bsel,
        const float4* msg4, const float4* h4, int c, int m0, int M, int tid) {
    int r = tid >> 3, j = tid & 7;
    const float4* s4 = (c < 4) ? msg4 : h4;
    int koff = (c & 3) * 8;
    float4 v = make_float4(0.f, 0.f, 0.f, 0.f);
    int grow = m0 + r;
    if (grow < M) v = s4[(size_t)grow * 32 + koff + j];
    uint32_t h0 = pack_h2(v.x, v.y), h1 = pack_h2(v.z, v.w);
    uint32_t dst = sbase + (uint32_t)(bsel * GRU2_BUF_U32 + r * 20 + 2 * j) * 4;
    asm volatile("st.shared.v2.b32 [%0], {%1,%2};" :: "r"(dst), "r"(h0), "r"(h1));
}

__device__ __forceinline__ void gru2_loadB(uint32_t sbase, int bsel,
        const uint4* w16, int c, int tid) {
    #pragma unroll
    for (int i = 0; i < 4; i++) {
        int id = tid + i * 512;     // [0,2048)
        int r = id >> 2, q = id & 3;
        if (c >= 4 || r < 384) {    // rows 384..511 are zero for k<128
            uint32_t dst = sbase +
                (uint32_t)(bsel * GRU2_BUF_U32 + 1280 + r * 20 + q * 4) * 4;
            const uint4* src = w16 + (size_t)r * 32 + c * 4 + q;
            asm volatile("cp.async.cg.shared.global [%0], [%1], 16;"
                         :: "r"(dst), "l"(src) : "memory");
        }
    }
    asm volatile("cp.async.commit_group;" ::: "memory");
}

__device__ __forceinline__ void gru2_compute(const uint32_t* dyn, int bsel,
        int rg, int cg, int lane, float acc[16][4]) {
    const uint32_t* A = dyn + bsel * GRU2_BUF_U32;
    const uint32_t* B = A + 1280;
    #pragma unroll
    for (int kt = 0; kt < 2; kt++) {
        int k1 = kt * 8 + (lane & 3);
        int ar = (rg * 16 + (lane >> 2)) * 20 + k1;
        uint32_t a0 = A[ar],           a1 = A[ar + 8 * 20];
        uint32_t a2 = A[ar + 4],       a3 = A[ar + 8 * 20 + 4];
        #pragma unroll
        for (int t = 0; t < 16; t++) {
            int br = (cg * 128 + t * 8 + (lane >> 2)) * 20 + k1;
            uint32_t b0 = B[br], b1 = B[br + 4];
            MMA_F16(acc[t], a0, a1, a2, a3, b0, b1);
        }
    }
}

__global__ void __launch_bounds__(512, 1)
k_gru2(const float* __restrict__ msg, const float* __restrict__ h_in,
       float* __restrict__ h_out, const uint32_t* __restrict__ wcat,
       const float* __restrict__ bih, const float* __restrict__ bhh, int M) {
    extern __shared__ uint32_t dyn[];
    int tid = threadIdx.x;
    int lane = tid & 31, wid = tid >> 5;
    int cg = wid >> 2;       // col group: 128 cat-cols (3=Hn)
    int rg = wid & 3;        // row group: 16 rows
    int m0 = blockIdx.x * 64;
    uint32_t sbase = smem_u32(dyn);

    const float4* msg4 = (const float4*)msg;
    const float4* h4   = (const float4*)h_in;
    const uint4*  w16  = (const uint4*)wcat;

    float acc[16][4];
    #pragma unroll
    for (int t = 0; t < 16; t++)
        #pragma unroll
        for (int i = 0; i < 4; i++) acc[t][i] = 0.f;

    gru2_loadA(sbase, 0, msg4, h4, 0, m0, M, tid);
    gru2_loadB(sbase, 0, w16, 0, tid);

    for (int c = 0; c < 8; c++) {
        if (c < 7) {
            gru2_loadA(sbase, (c + 1) & 1, msg4, h4, c + 1, m0, M, tid);
            gru2_loadB(sbase, (c + 1) & 1, w16, c + 1, tid);
            asm volatile("cp.async.wait_group 1;" ::: "memory");
        } else {
            asm volatile("cp.async.wait_group 0;" ::: "memory");
        }
        __syncthreads();
        if (cg < 3 || c >= 4)
            gru2_compute(dyn, c & 1, rg, cg, lane, acc);
        __syncthreads();
    }

    // write S to smem: [64][516] floats
    float* S = (float*)dyn;
    #pragma unroll
    for (int t = 0; t < 16; t++) {
        int n0 = cg * 128 + t * 8 + (lane & 3) * 2;
        int rb = rg * 16 + (lane >> 2);
        S[rb * 516 + n0]       = acc[t][0];
        S[rb * 516 + n0 + 1]   = acc[t][1];
        S[(rb + 8) * 516 + n0]     = acc[t][2];
        S[(rb + 8) * 516 + n0 + 1] = acc[t][3];
    }
    __syncthreads();

    // gate: 8 threads/row, 16 cols each (4x float4)
    int r = tid >> 3;
    int row = m0 + r;
    if (row < M) {
        const float4* bi4 = (const float4*)bih;
        const float4* bh4 = (const float4*)bhh;
        #pragma unroll
        for (int q = 0; q < 4; q++) {
            int g4 = (tid & 7) * 4 + q;          // 0..31
            float4 Sr = *(const float4*)(S + r * 516 + g4 * 4);
            float4 Sz = *(const float4*)(S + r * 516 + 128 + g4 * 4);
            float4 Sn = *(const float4*)(S + r * 516 + 256 + g4 * 4);
            float4 Hn = *(const float4*)(S + r * 516 + 384 + g4 * 4);
            float4 bir = bi4[g4], biz = bi4[32 + g4], bin_ = bi4[64 + g4];
            float4 bhr = bh4[g4], bhz = bh4[32 + g4], bhn = bh4[64 + g4];
            float4 hv = ((const float4*)h_in)[(size_t)row * 32 + g4];
            float4 o;
#define GG(cmp) { \
            float rr_ = sigmf(Sr.cmp + bir.cmp + bhr.cmp); \
            float zz_ = sigmf(Sz.cmp + biz.cmp + bhz.cmp); \
            float xn_ = Sn.cmp - Hn.cmp; \
            float nn_ = tanhf(xn_ + bin_.cmp + rr_ * (Hn.cmp + bhn.cmp)); \
            o.cmp = (1.f - zz_) * nn_ + zz_ * hv.cmp; }
            GG(x) GG(y) GG(z) GG(w)
#undef GG
            ((float4*)h_out)[(size_t)row * 32 + g4] = o;
        }
    }
}

// ---------------- final FC: 64 rows/block, dynamic smem ----------------
#define FC_SMEM_FLOATS (128 * 33 + 64 * 128)

__global__ void __launch_bounds__(256)
k_fc(const float* __restrict__ es, const float* __restrict__ fcw,
     const float* __restrict__ fcb, float* __restrict__ logits) {
    extern __shared__ float sf[];
    float* Wt = sf;                    // [128][33]
    float* rowbuf = sf + 128 * 33;     // [64][128]
    int tid = threadIdx.x;
    #pragma unroll
    for (int i = 0; i < 4; i++) {
        int idx = tid + i * 256;
        int j = idx >> 5, k4 = idx & 31;
        float4 w = ((const float4*)fcw)[j * 32 + k4];
        Wt[(k4 * 4 + 0) * 33 + j] = w.x; Wt[(k4 * 4 + 1) * 33 + j] = w.y;
        Wt[(k4 * 4 + 2) * 33 + j] = w.z; Wt[(k4 * 4 + 3) * 33 + j] = w.w;
    }
    int base = blockIdx.x * 64;
    #pragma unroll
    for (int i = 0; i < 8; i++) {
        int id = tid + i * 256;
        int r = id >> 5, f4 = id & 31;
        ((float4*)(rowbuf + r * 128))[f4] =
            ((const float4*)(es + (size_t)(base + r) * 128))[f4];
    }
    __syncthreads();
    int w = tid >> 5, lane = tid & 31;
    float acc[8];
    float b = fcb[lane];
    #pragma unroll
    for (int r = 0; r < 8; r++) acc[r] = b;
    for (int k = 0; k < 128; k++) {
        float wt = Wt[k * 33 + lane];
        #pragma unroll
        for (int r = 0; r < 8; r++)
            acc[r] += rowbuf[(w * 8 + r) * 128 + k] * wt;
    }
    #pragma unroll
    for (int r = 0; r < 8; r++)
        logits[(size_t)(base + w * 8 + r) * Cn + lane] = acc[r];
}

// ---------------- host orchestration ----------------
extern "C" void kernel_launch(void* const* d_in, const int* in_sizes, int n_in,
                              void* d_out, int out_size) {
    (void)in_sizes; (void)n_in; (void)out_size;
    const int*   seed_index = (const int*)d_in[0];
    const float* es_in  = (const float*)d_in[1];
    const float* ps_in  = (const float*)d_in[2];
    const int*   rows   = (const int*)d_in[3];
    const int*   cols   = (const int*)d_in[4];
    const float* vals   = (const float*)d_in[5];
    const float* fcw    = (const float*)d_in[22];
    const float* fcb    = (const float*)d_in[23];

    float* out       = (float*)d_out;
    float* out_logit = out;
    float* out_es    = out + (size_t)En * Cn;
    float* out_ps    = out_es + (size_t)En * Dn;

    cudaFuncSetAttribute(k_gru2, cudaFuncAttributeMaxDynamicSharedMemorySize, GRU2_SMEM);
    cudaFuncSetAttribute(k_fc, cudaFuncAttributeMaxDynamicSharedMemorySize,
                         FC_SMEM_FLOATS * 4);

    void *pOffP, *pOffE, *pEiP, *pEiE, *pPmsg, *pEmsg, *pWcat;
    cudaGetSymbolAddress(&pOffP, d_offP);
    cudaGetSymbolAddress(&pOffE, d_offE);
    cudaGetSymbolAddress(&pEiP, d_eiP);
    cudaGetSymbolAddress(&pEiE, d_eiE);
    cudaGetSymbolAddress(&pPmsg, d_pmsg);
    cudaGetSymbolAddress(&pEmsg, d_emsg);
    cudaGetSymbolAddress(&pWcat, d_wcat2);

    // CSR build
    k_zero_counts<<<(En + 255) / 256, 256>>>();
    k_count<<<(NNZn + 255) / 256, 256>>>(rows, cols);
    k_scan1<<<NBP + NBE, 1024>>>();
    k_scan2<<<2, 1024>>>();
    k_scan3<<<NBP + NBE, 1024>>>();
    k_fill<<<(NNZn + 255) / 256, 256>>>(rows, cols, vals);

    // all 4 GRU weight matrices, one launch (slots: l0_p, l0_e, l1_p, l1_e)
    k_wprep_all<<<2048, 128>>>(
        (const float*)d_in[10], (const float*)d_in[11],   // l0 p
        (const float*)d_in[6],  (const float*)d_in[7],    // l0 e
        (const float*)d_in[18], (const float*)d_in[19],   // l1 p
        (const float*)d_in[14], (const float*)d_in[15]);  // l1 e

    dim3 spmmB(32, 8);
    int gE = (En + 63) / 64;   // 3125
    int gP = (Pn + 63) / 64;   // 782

    for (int l = 0; l < 2; l++) {
        const float* ebih = (const float*)d_in[6 + l * 8 + 2];
        const float* ebhh = (const float*)d_in[6 + l * 8 + 3];
        const float* pbih = (const float*)d_in[6 + l * 8 + 6];
        const float* pbhh = (const float*)d_in[6 + l * 8 + 7];

        const float* es_cur = (l == 0) ? es_in : out_es;
        const float* ps_cur = (l == 0) ? ps_in : out_ps;

        const uint32_t* wP = (const uint32_t*)pWcat + (l * 2 + 0) * 65536;
        const uint32_t* wE = (const uint32_t*)pWcat + (l * 2 + 1) * 65536;

        k_seed_mean<<<1, dim3(128, 8)>>>(es_cur, seed_index);

        // p_msg = segment_sum(es[row]*w, col); ps = GRU(p_msg, ps)
        k_spmm<<<(Pn + 7) / 8, spmmB>>>((const float4*)es_cur, (float4*)pPmsg,
                                        (const int*)pOffP, (const int2*)pEiP, Pn, 0);
        k_gru2<<<gP, 512, GRU2_SMEM>>>((const float*)pPmsg, ps_cur, out_ps,
                                       wP, pbih, pbhh, Pn);

        // e_msg = segment_sum(ps[col]*w, row) + seed_mean; es = GRU(e_msg, es)
        k_spmm<<<(En + 7) / 8, spmmB>>>((const float4*)out_ps, (float4*)pEmsg,
                                        (const int*)pOffE, (const int2*)pEiE, En, 1);
        k_gru2<<<gE, 512, GRU2_SMEM>>>((const float*)pEmsg, es_cur, out_es,
                                       wE, ebih, ebhh, En);
    }

    k_fc<<<En / 64, 256, FC_SMEM_FLOATS * 4>>>(out_es, fcw, fcb, out_logit);
}

// round 9
// speedup vs baseline: 1.9862x; 1.1020x over previous
#include <cuda_runtime.h>
#include <cuda_fp16.h>
#include <math.h>
#include <stdint.h>

#define En     200000
#define Pn     50000
#define Dn     128
#define NNZn   2000000
#define Cn     32
#define NSEEDn 320
#define G3     384   // 3*D

// ---------------- scratch (device globals; no allocation allowed) ----------------
__device__ float d_pmsg[(size_t)Pn * Dn];
__device__ float d_emsg[(size_t)En * Dn];
__device__ float d_esB[(size_t)En * Dn];    // ping-pong for es
__device__ float d_psB[(size_t)Pn * Dn];    // ping-pong for ps
__device__ int   d_cntP[Pn];
__device__ int   d_offP[Pn + 1];
__device__ int   d_curP[Pn];
__device__ int   d_cntE[En];
__device__ int   d_offE[En + 1];
__device__ int   d_curE[En];
__device__ int2  d_eiP[NNZn];
__device__ int2  d_eiE[NNZn];
__device__ float d_smean[Dn];
__device__ int   d_partP[64];
__device__ int   d_partE[256];
// fp16 gate-grouped cat weights, 4 slots (l0_p, l0_e, l1_p, l1_e):
// wrow = gy*256 + g*64 + j  (gy: col-half, g: 0=r,1=z,2=xn,3=ghn, j: gate col in half)
// 128 half2 k-pairs per row (k<128: Wih part, k>=128: Whh part; zeros where unused)
__device__ uint32_t d_wcat3[4 * 512 * 128];

#define NBP ((Pn + 1023) / 1024)   // 49
#define NBE ((En + 1023) / 1024)   // 196

// ---------------- helpers ----------------
__device__ __forceinline__ uint32_t smem_u32(const void* p) {
    uint32_t a;
    asm("{ .reg .u64 t; cvta.to.shared.u64 t, %1; cvt.u32.u64 %0, t; }" : "=r"(a) : "l"(p));
    return a;
}
__device__ __forceinline__ float sigmf(float x) { return 1.f / (1.f + expf(-x)); }
__device__ __forceinline__ uint32_t pack_h2(float a, float b) {
    __half2 h = __floats2half2_rn(a, b);
    return *(uint32_t*)&h;
}

#define MMA_F16(acc, a0, a1, a2, a3, b0, b1)                                \
    asm volatile("mma.sync.aligned.m16n8k16.row.col.f32.f16.f16.f32 "       \
                 "{%0,%1,%2,%3}, {%4,%5,%6,%7}, {%8,%9}, {%0,%1,%2,%3};"    \
                 : "+f"(acc[0]), "+f"(acc[1]), "+f"(acc[2]), "+f"(acc[3])   \
                 : "r"(a0), "r"(a1), "r"(a2), "r"(a3), "r"(b0), "r"(b1));

// ---------------- CSR build ----------------
__global__ void k_zero_counts() {
    int i = blockIdx.x * blockDim.x + threadIdx.x;
    if (i < En) d_cntE[i] = 0;
    if (i < Pn) d_cntP[i] = 0;
}

__global__ void k_count(const int* __restrict__ rows, const int* __restrict__ cols) {
    int i = blockIdx.x * blockDim.x + threadIdx.x;
    if (i < NNZn) {
        atomicAdd(&d_cntE[rows[i]], 1);
        atomicAdd(&d_cntP[cols[i]], 1);
    }
}

__global__ void k_scan1() {
    __shared__ int s[1024];
    int isE = (blockIdx.x >= NBP);
    int b = isE ? blockIdx.x - NBP : blockIdx.x;
    const int* cnt = isE ? d_cntE : d_cntP;
    int* off = isE ? d_offE : d_offP;
    int* part = isE ? d_partE : d_partP;
    int n = isE ? En : Pn;
    int g = b * 1024 + threadIdx.x;
    s[threadIdx.x] = (g < n) ? cnt[g] : 0;
    __syncthreads();
    for (int o = 1; o < 1024; o <<= 1) {
        int t = (threadIdx.x >= o) ? s[threadIdx.x - o] : 0;
        __syncthreads();
        s[threadIdx.x] += t;
        __syncthreads();
    }
    if (g < n) off[g + 1] = s[threadIdx.x];
    if (threadIdx.x == 1023) part[b] = s[1023];
    if (g == 0) off[0] = 0;
}

__global__ void k_scan2() {
    __shared__ int s[1024];
    int isE = (blockIdx.x == 1);
    int* part = isE ? d_partE : d_partP;
    int n = isE ? NBE : NBP;
    s[threadIdx.x] = (threadIdx.x < n) ? part[threadIdx.x] : 0;
    __syncthreads();
    for (int o = 1; o < 1024; o <<= 1) {
        int t = (threadIdx.x >= o) ? s[threadIdx.x - o] : 0;
        __syncthreads();
        s[threadIdx.x] += t;
        __syncthreads();
    }
    if (threadIdx.x < n)
        part[threadIdx.x] = (threadIdx.x == 0) ? 0 : s[threadIdx.x - 1];
}

__global__ void k_scan3() {
    int isE = (blockIdx.x >= NBP);
    int b = isE ? blockIdx.x - NBP : blockIdx.x;
    int* off = isE ? d_offE : d_offP;
    int* cur = isE ? d_curE : d_curP;
    const int* part = isE ? d_partE : d_partP;
    int n = isE ? En : Pn;
    int g = b * 1024 + threadIdx.x;
    if (g < n) {
        int v = off[g + 1] + part[b];
        off[g + 1] = v;
        if (g + 1 < n) cur[g + 1] = v;
    }
    if (g == 0) cur[0] = 0;
}

__global__ void k_fill(const int* __restrict__ rows, const int* __restrict__ cols,
                       const float* __restrict__ vals) {
    int i = blockIdx.x * blockDim.x + threadIdx.x;
    if (i < NNZn) {
        int r = rows[i], c = cols[i];
        int vb = __float_as_int(vals[i]);
        int pp = atomicAdd(&d_curP[c], 1);
        d_eiP[pp] = make_int2(r, vb);
        int pe = atomicAdd(&d_curE[r], 1);
        d_eiE[pe] = make_int2(c, vb);
    }
}

// ---------------- seed mean ----------------
__global__ void k_seed_mean(const float* __restrict__ es, const int* __restrict__ sidx) {
    __shared__ float red[8][128];
    int d = threadIdx.x, ty = threadIdx.y;
    float s = 0.f;
    for (int i = ty; i < NSEEDn; i += 8)
        s += es[(size_t)sidx[i] * Dn + d];
    red[ty][d] = s;
    __syncthreads();
    if (ty == 0) {
        float tot = 0.f;
        #pragma unroll
        for (int j = 0; j < 8; j++) tot += red[j][d];
        d_smean[d] = tot * (1.f / NSEEDn);
    }
}

// ---------------- SpMM: one warp per segment ----------------
__global__ void k_spmm(const float4* __restrict__ src, float4* __restrict__ dst,
                       const int* __restrict__ off, const int2* __restrict__ ei,
                       int nseg, int add_smean) {
    int seg = blockIdx.x * 8 + threadIdx.y;
    if (seg >= nseg) return;
    int lane = threadIdx.x;
    float4 acc;
    if (add_smean) acc = ((const float4*)d_smean)[lane];
    else           acc = make_float4(0.f, 0.f, 0.f, 0.f);
    int b = off[seg], e = off[seg + 1];
    int t = b;
    for (; t + 4 <= e; t += 4) {
        int2 e0 = ei[t], e1 = ei[t + 1], e2 = ei[t + 2], e3 = ei[t + 3];
        float4 x0 = src[(size_t)e0.x * 32 + lane];
        float4 x1 = src[(size_t)e1.x * 32 + lane];
        float4 x2 = src[(size_t)e2.x * 32 + lane];
        float4 x3 = src[(size_t)e3.x * 32 + lane];
        float v0 = __int_as_float(e0.y), v1 = __int_as_float(e1.y);
        float v2 = __int_as_float(e2.y), v3 = __int_as_float(e3.y);
        acc.x += x0.x * v0 + x1.x * v1 + x2.x * v2 + x3.x * v3;
        acc.y += x0.y * v0 + x1.y * v1 + x2.y * v2 + x3.y * v3;
        acc.z += x0.z * v0 + x1.z * v1 + x2.z * v2 + x3.z * v3;
        acc.w += x0.w * v0 + x1.w * v1 + x2.w * v2 + x3.w * v3;
    }
    for (; t < e; t++) {
        int2 e0 = ei[t];
        float v0 = __int_as_float(e0.y);
        float4 x0 = src[(size_t)e0.x * 32 + lane];
        acc.x += x0.x * v0; acc.y += x0.y * v0;
        acc.z += x0.z * v0; acc.w += x0.w * v0;
    }
    dst[(size_t)seg * 32 + lane] = acc;
}

// ---------------- weight prep: gate-grouped cat matrices, fp16 ----------------
__global__ void k_wprep_all(
    const float* __restrict__ p0ih, const float* __restrict__ p0hh,
    const float* __restrict__ e0ih, const float* __restrict__ e0hh,
    const float* __restrict__ p1ih, const float* __restrict__ p1hh,
    const float* __restrict__ e1ih, const float* __restrict__ e1hh) {
    int slot = blockIdx.x >> 9;       // 0..3
    int wrow = blockIdx.x & 511;      // 0..511
    int p = threadIdx.x;              // k-pair 0..127
    const float* Wih;
    const float* Whh;
    switch (slot) {
        case 0: Wih = p0ih; Whh = p0hh; break;
        case 1: Wih = e0ih; Whh = e0hh; break;
        case 2: Wih = p1ih; Whh = p1hh; break;
        default: Wih = e1ih; Whh = e1hh; break;
    }
    int gy = wrow >> 8, rem = wrow & 255;
    int g = rem >> 6, j = rem & 63;
    int gc = gy * 64 + j;             // gate col 0..127
    int k0 = 2 * p, k1 = 2 * p + 1;
    float v0 = 0.f, v1 = 0.f;
    if (g == 0 || g == 1) {           // r or z: full K
        int row = g * 128 + gc;
        v0 = (k0 < 128) ? Wih[row * 128 + k0] : Whh[row * 128 + (k0 - 128)];
        v1 = (k1 < 128) ? Wih[row * 128 + k1] : Whh[row * 128 + (k1 - 128)];
    } else if (g == 2) {              // xn: Wih_n only (k<128)
        int row = 256 + gc;
        if (k0 < 128) v0 = Wih[row * 128 + k0];
        if (k1 < 128) v1 = Wih[row * 128 + k1];
    } else {                          // ghn: Whh_n only (k>=128)
        int row = 256 + gc;
        if (k0 >= 128) v0 = Whh[row * 128 + (k0 - 128)];
        if (k1 >= 128) v1 = Whh[row * 128 + (k1 - 128)];
    }
    d_wcat3[slot * 65536 + wrow * 128 + p] = pack_h2(v0, v1);
}

// ---------------- GRU v3: 128 rows x 64 gate-cols per block, in-register gate --------
// smem (u32): per buffer: A 128*20=2560, B 192*20=3840 -> 6400; x2 = 12800 u32 = 51200 B
// epilogue h-stage: 128*68 floats = 34816 B (overlaps pipeline region)
#define GRU3_BUF_U32 6400
#define GRU3_SMEM    51200

__device__ __forceinline__ void gru3_loadA(uint32_t sbase, int bsel,
        const float4* msg4, const float4* h4, int c, int m0, int M, int tid) {
    #pragma unroll
    for (int i = 0; i < 2; i++) {
        int id = tid + i * 512;          // [0,1024)
        int r = id >> 3, j = id & 7;
        const float4* s4 = (c < 4) ? msg4 : h4;
        int koff = (c & 3) * 8;
        float4 v = make_float4(0.f, 0.f, 0.f, 0.f);
        int grow = m0 + r;
        if (grow < M) v = s4[(size_t)grow * 32 + koff + j];
        uint32_t h0 = pack_h2(v.x, v.y), h1 = pack_h2(v.z, v.w);
        uint32_t dst = sbase + (uint32_t)(bsel * GRU3_BUF_U32 + r * 20 + 2 * j) * 4;
        asm volatile("st.shared.v2.b32 [%0], {%1,%2};" :: "r"(dst), "r"(h0), "r"(h1));
    }
}

__device__ __forceinline__ void gru3_loadB(uint32_t sbase, int bsel,
        const uint4* w16, int c, int gy, int tid) {
    #pragma unroll
    for (int i = 0; i < 2; i++) {
        int id = tid + i * 512;          // [0,1024), use [0,768)
        if (id < 768) {
            int rp = id >> 2, q = id & 3;    // dense row 0..191, quad 0..3
            int blkrow = (c < 4) ? rp : ((rp < 128) ? rp : rp + 64);
            uint32_t dst = sbase +
                (uint32_t)(bsel * GRU3_BUF_U32 + 2560 + rp * 20 + q * 4) * 4;
            const uint4* src = w16 + (size_t)(gy * 256 + blkrow) * 32 + c * 4 + q;
            asm volatile("cp.async.cg.shared.global [%0], [%1], 16;"
                         :: "r"(dst), "l"(src) : "memory");
        }
    }
    asm volatile("cp.async.commit_group;" ::: "memory");
}

__device__ __forceinline__ void gru3_compute(const uint32_t* dyn, int bsel,
        int rg, int cs, int lane, int c, float acc[16][4]) {
    const uint32_t* A = dyn + bsel * GRU3_BUF_U32;
    const uint32_t* B = A + 2560;
    #pragma unroll
    for (int kt = 0; kt < 2; kt++) {
        int k1 = kt * 8 + (lane & 3);
        #pragma unroll
        for (int rsub = 0; rsub < 2; rsub++) {
            int ar = (rg * 32 + rsub * 16 + (lane >> 2)) * 20 + k1;
            uint32_t a0 = A[ar],     a1 = A[ar + 8 * 20];
            uint32_t a2 = A[ar + 4], a3 = A[ar + 8 * 20 + 4];
            #pragma unroll
            for (int g = 0; g < 4; g++) {
                if (g == 2 && c >= 4) continue;
                if (g == 3 && c < 4) continue;
                #pragma unroll
                for (int ct = 0; ct < 2; ct++) {
                    int local = cs * 16 + ct * 8 + (lane >> 2);
                    int srow = (g < 2) ? g * 64 + local : 128 + local;
                    int br = srow * 20 + k1;
                    uint32_t b0 = B[br], b1 = B[br + 4];
                    MMA_F16(acc[g * 4 + rsub * 2 + ct], a0, a1, a2, a3, b0, b1);
                }
            }
        }
    }
}

__global__ void __launch_bounds__(512, 1)
k_gru3(const float* __restrict__ msg, const float* __restrict__ h_in,
       float* __restrict__ h_out, const uint32_t* __restrict__ wcat,
       const float* __restrict__ bih, const float* __restrict__ bhh, int M) {
    extern __shared__ uint32_t dyn[];
    int tid = threadIdx.x;
    int lane = tid & 31, wid = tid >> 5;
    int rg = wid >> 2;       // row group: 32 rows
    int cs = wid & 3;        // col slice: 16 gate cols
    int m0 = blockIdx.x * 128;
    int gy = blockIdx.y;     // gate-col half
    uint32_t sbase = smem_u32(dyn);

    const float4* msg4 = (const float4*)msg;
    const float4* h4   = (const float4*)h_in;
    const uint4*  w16  = (const uint4*)wcat;

    float acc[16][4];
    #pragma unroll
    for (int t = 0; t < 16; t++)
        #pragma unroll
        for (int i = 0; i < 4; i++) acc[t][i] = 0.f;

    gru3_loadA(sbase, 0, msg4, h4, 0, m0, M, tid);
    gru3_loadB(sbase, 0, w16, 0, gy, tid);

    for (int c = 0; c < 8; c++) {
        if (c < 7) {
            gru3_loadA(sbase, (c + 1) & 1, msg4, h4, c + 1, m0, M, tid);
            gru3_loadB(sbase, (c + 1) & 1, w16, c + 1, gy, tid);
            asm volatile("cp.async.wait_group 1;" ::: "memory");
        } else {
            asm volatile("cp.async.wait_group 0;" ::: "memory");
        }
        __syncthreads();
        gru3_compute(dyn, c & 1, rg, cs, lane, c, acc);
        __syncthreads();
    }

    // stage h_in block cols into smem (coalesced), stride 68
    float* hs = (float*)dyn;
    #pragma unroll
    for (int i = 0; i < 4; i++) {
        int id = tid + i * 512;          // [0,2048)
        int r = id >> 4, f = id & 15;
        int row = m0 + r;
        float4 v = make_float4(0.f, 0.f, 0.f, 0.f);
        if (row < M) v = h4[(size_t)row * 32 + gy * 16 + f];
        *(float4*)(hs + r * 68 + f * 4) = v;
    }
    __syncthreads();

    // in-register gate, result into hs
    #pragma unroll
    for (int rsub = 0; rsub < 2; rsub++) {
        #pragma unroll
        for (int ct = 0; ct < 2; ct++) {
            #pragma unroll
            for (int i = 0; i < 4; i++) {
                int row_l = rg * 32 + rsub * 16 + (lane >> 2) + (i >> 1) * 8;
                int col_l = cs * 16 + ct * 8 + (lane & 3) * 2 + (i & 1);
                int gcol = gy * 64 + col_l;
                float Sr = acc[0 + rsub * 2 + ct][i];
                float Sz = acc[4 + rsub * 2 + ct][i];
                float Xn = acc[8 + rsub * 2 + ct][i];
                float Gn = acc[12 + rsub * 2 + ct][i];
                float r_ = sigmf(Sr + __ldg(bih + gcol) + __ldg(bhh + gcol));
                float z_ = sigmf(Sz + __ldg(bih + 128 + gcol) + __ldg(bhh + 128 + gcol));
                float n_ = tanhf(Xn + __ldg(bih + 256 + gcol) +
                                 r_ * (Gn + __ldg(bhh + 256 + gcol)));
                float hv = hs[row_l * 68 + col_l];
                hs[row_l * 68 + col_l] = (1.f - z_) * n_ + z_ * hv;
            }
        }
    }
    __syncthreads();

    // coalesced writeout
    #pragma unroll
    for (int i = 0; i < 4; i++) {
        int id = tid + i * 512;
        int r = id >> 4, f = id & 15;
        int row = m0 + r;
        if (row < M)
            ((float4*)h_out)[(size_t)row * 32 + gy * 16 + f] =
                *(float4*)(hs + r * 68 + f * 4);
    }
}

// ---------------- final FC: 64 rows/block, dynamic smem ----------------
#define FC_SMEM_FLOATS (128 * 33 + 64 * 128)

__global__ void __launch_bounds__(256)
k_fc(const float* __restrict__ es, const float* __restrict__ fcw,
     const float* __restrict__ fcb, float* __restrict__ logits) {
    extern __shared__ float sf[];
    float* Wt = sf;
    float* rowbuf = sf + 128 * 33;
    int tid = threadIdx.x;
    #pragma unroll
    for (int i = 0; i < 4; i++) {
        int idx = tid + i * 256;
        int j = idx >> 5, k4 = idx & 31;
        float4 w = ((const float4*)fcw)[j * 32 + k4];
        Wt[(k4 * 4 + 0) * 33 + j] = w.x; Wt[(k4 * 4 + 1) * 33 + j] = w.y;
        Wt[(k4 * 4 + 2) * 33 + j] = w.z; Wt[(k4 * 4 + 3) * 33 + j] = w.w;
    }
    int base = blockIdx.x * 64;
    #pragma unroll
    for (int i = 0; i < 8; i++) {
        int id = tid + i * 256;
        int r = id >> 5, f4 = id & 31;
        ((float4*)(rowbuf + r * 128))[f4] =
            ((const float4*)(es + (size_t)(base + r) * 128))[f4];
    }
    __syncthreads();
    int w = tid >> 5, lane = tid & 31;
    float acc[8];
    float b = fcb[lane];
    #pragma unroll
    for (int r = 0; r < 8; r++) acc[r] = b;
    for (int k = 0; k < 128; k++) {
        float wt = Wt[k * 33 + lane];
        #pragma unroll
        for (int r = 0; r < 8; r++)
            acc[r] += rowbuf[(w * 8 + r) * 128 + k] * wt;
    }
    #pragma unroll
    for (int r = 0; r < 8; r++)
        logits[(size_t)(base + w * 8 + r) * Cn + lane] = acc[r];
}

// ---------------- host orchestration ----------------
extern "C" void kernel_launch(void* const* d_in, const int* in_sizes, int n_in,
                              void* d_out, int out_size) {
    (void)in_sizes; (void)n_in; (void)out_size;
    const int*   seed_index = (const int*)d_in[0];
    const float* es_in  = (const float*)d_in[1];
    const float* ps_in  = (const float*)d_in[2];
    const int*   rows   = (const int*)d_in[3];
    const int*   cols   = (const int*)d_in[4];
    const float* vals   = (const float*)d_in[5];
    const float* fcw    = (const float*)d_in[22];
    const float* fcb    = (const float*)d_in[23];

    float* out       = (float*)d_out;
    float* out_logit = out;
    float* out_es    = out + (size_t)En * Cn;
    float* out_ps    = out_es + (size_t)En * Dn;

    cudaFuncSetAttribute(k_gru3, cudaFuncAttributeMaxDynamicSharedMemorySize, GRU3_SMEM);
    cudaFuncSetAttribute(k_fc, cudaFuncAttributeMaxDynamicSharedMemorySize,
                         FC_SMEM_FLOATS * 4);

    void *pOffP, *pOffE, *pEiP, *pEiE, *pPmsg, *pEmsg, *pWcat, *pEsB, *pPsB;
    cudaGetSymbolAddress(&pOffP, d_offP);
    cudaGetSymbolAddress(&pOffE, d_offE);
    cudaGetSymbolAddress(&pEiP, d_eiP);
    cudaGetSymbolAddress(&pEiE, d_eiE);
    cudaGetSymbolAddress(&pPmsg, d_pmsg);
    cudaGetSymbolAddress(&pEmsg, d_emsg);
    cudaGetSymbolAddress(&pWcat, d_wcat3);
    cudaGetSymbolAddress(&pEsB, d_esB);
    cudaGetSymbolAddress(&pPsB, d_psB);

    // CSR build
    k_zero_counts<<<(En + 255) / 256, 256>>>();
    k_count<<<(NNZn + 255) / 256, 256>>>(rows, cols);
    k_scan1<<<NBP + NBE, 1024>>>();
    k_scan2<<<2, 1024>>>();
    k_scan3<<<NBP + NBE, 1024>>>();
    k_fill<<<(NNZn + 255) / 256, 256>>>(rows, cols, vals);

    // all 4 GRU weight matrices (slots: l0_p, l0_e, l1_p, l1_e)
    k_wprep_all<<<2048, 128>>>(
        (const float*)d_in[10], (const float*)d_in[11],   // l0 p
        (const float*)d_in[6],  (const float*)d_in[7],    // l0 e
        (const float*)d_in[18], (const float*)d_in[19],   // l1 p
        (const float*)d_in[14], (const float*)d_in[15]);  // l1 e

    dim3 spmmB(32, 8);
    dim3 gE((En + 127) / 128, 2);   // 1563 x 2
    dim3 gP((Pn + 127) / 128, 2);   // 391 x 2

    for (int l = 0; l < 2; l++) {
        const float* ebih = (const float*)d_in[6 + l * 8 + 2];
        const float* ebhh = (const float*)d_in[6 + l * 8 + 3];
        const float* pbih = (const float*)d_in[6 + l * 8 + 6];
        const float* pbhh = (const float*)d_in[6 + l * 8 + 7];

        // ping-pong: l0: es_in->esB, ps_in->psB; l1: esB->out_es, psB->out_ps
        const float* es_cur = (l == 0) ? es_in : (const float*)pEsB;
        const float* ps_cur = (l == 0) ? ps_in : (const float*)pPsB;
        float* es_nxt = (l == 0) ? (float*)pEsB : out_es;
        float* ps_nxt = (l == 0) ? (float*)pPsB : out_ps;

        const uint32_t* wP = (const uint32_t*)pWcat + (l * 2 + 0) * 65536;
        const uint32_t* wE = (const uint32_t*)pWcat + (l * 2 + 1) * 65536;

        k_seed_mean<<<1, dim3(128, 8)>>>(es_cur, seed_index);

        k_spmm<<<(Pn + 7) / 8, spmmB>>>((const float4*)es_cur, (float4*)pPmsg,
                                        (const int*)pOffP, (const int2*)pEiP, Pn, 0);
        k_gru3<<<gP, 512, GRU3_SMEM>>>((const float*)pPmsg, ps_cur, ps_nxt,
                                       wP, pbih, pbhh, Pn);

        k_spmm<<<(En + 7) / 8, spmmB>>>((const float4*)ps_nxt, (float4*)pEmsg,
                                        (const int*)pOffE, (const int2*)pEiE, En, 1);
        k_gru3<<<gE, 512, GRU3_SMEM>>>((const float*)pEmsg, es_cur, es_nxt,
                                       wE, ebih, ebhh, En);
    }

    k_fc<<<En / 64, 256, FC_SMEM_FLOATS * 4>>>(out_es, fcw, fcb, out_logit);
}